// round 1
// baseline (speedup 1.0000x reference)
#include <cuda_runtime.h>
#include <math.h>

// Problem constants
#define BB 4
#define SS 2048
#define DD 1024
#define FF 4096
#define HH 16
// SCALE = sqrt(1024/16) = 8 -> multiply scores by 0.125
#define INV_SCALE 0.125f
#define NEGBIG -1e30f

// ---------------- scratch (static device allocations; no cudaMalloc) ----------
__device__ float g_xln[BB*SS*DD];
__device__ float g_q  [BB*SS*DD];
__device__ float g_k  [BB*SS*DD];
__device__ float g_v  [BB*SS*DD];
__device__ float g_ctx[BB*SS*DD];
__device__ float g_x2 [BB*SS*DD];
__device__ float g_y  [BB*SS*DD];
__device__ float g_h  [BB*SS*FF];

// ---------------- LayerNorm: one block per row, 256 threads, D=1024 -----------
__global__ __launch_bounds__(256)
void ln_kernel(const float* __restrict__ x, const float* __restrict__ g,
               const float* __restrict__ b, float* __restrict__ out)
{
    int row = blockIdx.x;
    int tid = threadIdx.x;
    const float* xr = x + (size_t)row * DD;
    float4 v = *reinterpret_cast<const float4*>(xr + tid * 4);
    float s  = v.x + v.y + v.z + v.w;
    float sq = v.x*v.x + v.y*v.y + v.z*v.z + v.w*v.w;
    // warp reduce
    #pragma unroll
    for (int o = 16; o > 0; o >>= 1) {
        s  += __shfl_xor_sync(0xffffffffu, s,  o);
        sq += __shfl_xor_sync(0xffffffffu, sq, o);
    }
    __shared__ float ws[8], wq[8];
    __shared__ float smean, srstd;
    int wid = tid >> 5, lane = tid & 31;
    if (lane == 0) { ws[wid] = s; wq[wid] = sq; }
    __syncthreads();
    if (tid == 0) {
        float S = 0.f, Q = 0.f;
        #pragma unroll
        for (int i = 0; i < 8; i++) { S += ws[i]; Q += wq[i]; }
        float mean = S * (1.f / DD);
        float var  = fmaxf(Q * (1.f / DD) - mean * mean, 0.f);
        smean = mean;
        srstd = rsqrtf(var + 1e-12f);
    }
    __syncthreads();
    float mean = smean, rstd = srstd;
    float4 gv = *reinterpret_cast<const float4*>(g + tid * 4);
    float4 bv = *reinterpret_cast<const float4*>(b + tid * 4);
    float4 ov;
    ov.x = (v.x - mean) * rstd * gv.x + bv.x;
    ov.y = (v.y - mean) * rstd * gv.y + bv.y;
    ov.z = (v.z - mean) * rstd * gv.z + bv.z;
    ov.w = (v.w - mean) * rstd * gv.w + bv.w;
    *reinterpret_cast<float4*>(out + (size_t)row * DD + tid * 4) = ov;
}

// ---------------- SGEMM: C[M,N] = A[M,K] @ B[K,N] (+bias)(silu)(+res) ---------
// 128x128 tile, BK=16, 256 threads, 8x8 per thread.
__global__ __launch_bounds__(256, 2)
void gemm128(const float* __restrict__ A, const float* __restrict__ Bm,
             const float* __restrict__ bias, const float* __restrict__ res,
             float* __restrict__ C, int M, int N, int K, int act)
{
    __shared__ float As[16][128];
    __shared__ float Bs[16][128];
    int tid = threadIdx.x;
    int m0 = blockIdx.y * 128, n0 = blockIdx.x * 128;
    int tr = tid >> 4, tc = tid & 15;
    float acc[8][8];
    #pragma unroll
    for (int i = 0; i < 8; i++)
        #pragma unroll
        for (int j = 0; j < 8; j++) acc[i][j] = 0.f;

    const float* Ap = A + (size_t)m0 * K;
    const float* Bp = Bm + n0;

    for (int k0 = 0; k0 < K; k0 += 16) {
        // Load A tile 128x16 (transpose into As[k][m])
        #pragma unroll
        for (int t = 0; t < 2; t++) {
            int f  = tid + t * 256;      // float4 index, 512 total
            int r  = f >> 2;
            int c4 = (f & 3) << 2;
            float4 av = *reinterpret_cast<const float4*>(Ap + (size_t)r * K + k0 + c4);
            As[c4 + 0][r] = av.x; As[c4 + 1][r] = av.y;
            As[c4 + 2][r] = av.z; As[c4 + 3][r] = av.w;
        }
        // Load B tile 16x128 (natural Bs[k][n])
        #pragma unroll
        for (int t = 0; t < 2; t++) {
            int f  = tid + t * 256;
            int r  = f >> 5;
            int c4 = (f & 31) << 2;
            *reinterpret_cast<float4*>(&Bs[r][c4]) =
                *reinterpret_cast<const float4*>(Bp + (size_t)(k0 + r) * N + c4);
        }
        __syncthreads();
        #pragma unroll
        for (int kk = 0; kk < 16; kk++) {
            float a[8], bq[8];
            #pragma unroll
            for (int i = 0; i < 8; i++) a[i]  = As[kk][tr * 8 + i];
            #pragma unroll
            for (int j = 0; j < 8; j++) bq[j] = Bs[kk][tc * 8 + j];
            #pragma unroll
            for (int i = 0; i < 8; i++)
                #pragma unroll
                for (int j = 0; j < 8; j++) acc[i][j] += a[i] * bq[j];
        }
        __syncthreads();
    }

    // Epilogue
    #pragma unroll
    for (int i = 0; i < 8; i++) {
        int r = m0 + tr * 8 + i;
        size_t rowoff = (size_t)r * N;
        #pragma unroll
        for (int j = 0; j < 8; j++) {
            int c = n0 + tc * 8 + j;
            float val = acc[i][j];
            if (bias) val += bias[c];
            if (act)  val = val / (1.f + expf(-val));   // SiLU
            if (res)  val += res[rowoff + c];
            C[rowoff + c] = val;
        }
    }
}

// ---------------- Flash attention, fp32, causal + key pad mask ----------------
// Block: 64 query rows of one (b,h); 256 threads as 16x16 grid, 4x4 microtile.
#define ATTN_SMEM_FLOATS (4*64*64 + 64*16 + 4*64)
#define ATTN_SMEM_BYTES  (ATTN_SMEM_FLOATS * 4)

__global__ __launch_bounds__(256)
void attn_kernel(const float* __restrict__ q, const float* __restrict__ k,
                 const float* __restrict__ v, const int* __restrict__ amask,
                 float* __restrict__ ctx)
{
    extern __shared__ float sm[];
    float (*Qs)[64]  = (float(*)[64])(sm);           // [d][r]
    float (*Ks)[64]  = (float(*)[64])(sm + 4096);    // [d][c]
    float (*Vs)[64]  = (float(*)[64])(sm + 8192);    // [c][n]
    float (*Ps)[64]  = (float(*)[64])(sm + 12288);   // [c][r]
    float (*red)[16] = (float(*)[16])(sm + 16384);   // [64][16]
    float* mrow = sm + 16384 + 1024;
    float* lrow = mrow + 64;
    float* arow = lrow + 64;
    float* koff = arow + 64;

    int tid = threadIdx.x;
    int bh  = blockIdx.y;
    int b   = bh >> 4, h = bh & 15;
    int q0  = blockIdx.x * 64;
    int tr  = tid >> 4, tc = tid & 15;
    const size_t base = ((size_t)b * SS) * DD + (size_t)h * 64;

    // Load Q tile transposed (once)
    #pragma unroll
    for (int t = 0; t < 4; t++) {
        int f  = tid + t * 256;     // float4 index; 64 rows x 16 f4
        int r  = f >> 4;
        int c4 = (f & 15) << 2;
        float4 qv = *reinterpret_cast<const float4*>(q + base + (size_t)(q0 + r) * DD + c4);
        Qs[c4 + 0][r] = qv.x; Qs[c4 + 1][r] = qv.y;
        Qs[c4 + 2][r] = qv.z; Qs[c4 + 3][r] = qv.w;
    }
    if (tid < 64) { mrow[tid] = NEGBIG; lrow[tid] = 0.f; }

    float acc[4][4];
    #pragma unroll
    for (int i = 0; i < 4; i++)
        #pragma unroll
        for (int j = 0; j < 4; j++) acc[i][j] = 0.f;

    for (int kt = 0; kt <= blockIdx.x; kt++) {
        int k0 = kt * 64;
        __syncthreads();   // smem tiles free for reuse (also covers initial Q load)

        // Load K transposed, V natural
        #pragma unroll
        for (int t = 0; t < 4; t++) {
            int f  = tid + t * 256;
            int r  = f >> 4;
            int c4 = (f & 15) << 2;
            float4 kv = *reinterpret_cast<const float4*>(k + base + (size_t)(k0 + r) * DD + c4);
            Ks[c4 + 0][r] = kv.x; Ks[c4 + 1][r] = kv.y;
            Ks[c4 + 2][r] = kv.z; Ks[c4 + 3][r] = kv.w;
            float4 vv = *reinterpret_cast<const float4*>(v + base + (size_t)(k0 + r) * DD + c4);
            *reinterpret_cast<float4*>(&Vs[r][c4]) = vv;
        }
        if (tid < 64)
            koff[tid] = (amask[b * SS + k0 + tid] == 1) ? 0.f : NEGBIG;
        __syncthreads();

        // S = Q K^T
        float s[4][4];
        #pragma unroll
        for (int i = 0; i < 4; i++)
            #pragma unroll
            for (int j = 0; j < 4; j++) s[i][j] = 0.f;
        #pragma unroll 8
        for (int kk = 0; kk < 64; kk++) {
            float a[4], bq[4];
            #pragma unroll
            for (int i = 0; i < 4; i++) a[i]  = Qs[kk][tr * 4 + i];
            #pragma unroll
            for (int j = 0; j < 4; j++) bq[j] = Ks[kk][tc * 4 + j];
            #pragma unroll
            for (int i = 0; i < 4; i++)
                #pragma unroll
                for (int j = 0; j < 4; j++) s[i][j] += a[i] * bq[j];
        }

        // scale + mask + partial row max
        float pmax[4];
        #pragma unroll
        for (int i = 0; i < 4; i++) {
            pmax[i] = NEGBIG;
            int qi = q0 + tr * 4 + i;
            #pragma unroll
            for (int j = 0; j < 4; j++) {
                int kj = k0 + tc * 4 + j;
                float x = s[i][j] * INV_SCALE + koff[tc * 4 + j];
                if (kj > qi) x = NEGBIG;
                s[i][j] = x;
                pmax[i] = fmaxf(pmax[i], x);
            }
        }
        #pragma unroll
        for (int i = 0; i < 4; i++) red[tr * 4 + i][tc] = pmax[i];
        __syncthreads();
        if (tid < 64) {
            float mx = NEGBIG;
            #pragma unroll
            for (int t = 0; t < 16; t++) mx = fmaxf(mx, red[tid][t]);
            float mnew = fmaxf(mrow[tid], mx);
            arow[tid] = __expf(mrow[tid] - mnew);
            mrow[tid] = mnew;
        }
        __syncthreads();

        // P = exp(S - m), store transposed; partial row sums
        float psum[4];
        #pragma unroll
        for (int i = 0; i < 4; i++) {
            float mi = mrow[tr * 4 + i];
            psum[i] = 0.f;
            #pragma unroll
            for (int j = 0; j < 4; j++) {
                float p = __expf(s[i][j] - mi);
                Ps[tc * 4 + j][tr * 4 + i] = p;
                psum[i] += p;
            }
        }
        #pragma unroll
        for (int i = 0; i < 4; i++) red[tr * 4 + i][tc] = psum[i];
        __syncthreads();
        if (tid < 64) {
            float sm_ = 0.f;
            #pragma unroll
            for (int t = 0; t < 16; t++) sm_ += red[tid][t];
            lrow[tid] = lrow[tid] * arow[tid] + sm_;
        }

        // O = O*alpha + P @ V   (arow stable: written before last-but-one sync)
        float al[4];
        #pragma unroll
        for (int i = 0; i < 4; i++) al[i] = arow[tr * 4 + i];
        #pragma unroll
        for (int i = 0; i < 4; i++)
            #pragma unroll
            for (int j = 0; j < 4; j++) acc[i][j] *= al[i];
        #pragma unroll 8
        for (int kk = 0; kk < 64; kk++) {
            float a[4], bq[4];
            #pragma unroll
            for (int i = 0; i < 4; i++) a[i]  = Ps[kk][tr * 4 + i];
            #pragma unroll
            for (int j = 0; j < 4; j++) bq[j] = Vs[kk][tc * 4 + j];
            #pragma unroll
            for (int i = 0; i < 4; i++)
                #pragma unroll
                for (int j = 0; j < 4; j++) acc[i][j] += a[i] * bq[j];
        }
    }
    __syncthreads();   // lrow final

    #pragma unroll
    for (int i = 0; i < 4; i++) {
        float inv = 1.f / lrow[tr * 4 + i];
        float4 ov;
        ov.x = acc[i][0] * inv; ov.y = acc[i][1] * inv;
        ov.z = acc[i][2] * inv; ov.w = acc[i][3] * inv;
        *reinterpret_cast<float4*>(ctx + base + (size_t)(q0 + tr * 4 + i) * DD + tc * 4) = ov;
    }
}

// ---------------- host ---------------------------------------------------------
extern "C" void kernel_launch(void* const* d_in, const int* in_sizes, int n_in,
                              void* d_out, int out_size)
{
    const float* hidden = (const float*)d_in[0];
    const int*   amask  = (const int*)  d_in[1];
    const float* Wq     = (const float*)d_in[2];
    const float* Wk     = (const float*)d_in[3];
    const float* Wv     = (const float*)d_in[4];
    const float* Wo     = (const float*)d_in[5];
    const float* ln1g   = (const float*)d_in[6];
    const float* ln1b   = (const float*)d_in[7];
    const float* W1     = (const float*)d_in[8];
    const float* b1     = (const float*)d_in[9];
    const float* W2     = (const float*)d_in[10];
    const float* b2     = (const float*)d_in[11];
    const float* ln2g   = (const float*)d_in[12];
    const float* ln2b   = (const float*)d_in[13];
    float* out = (float*)d_out;

    float *xln, *qb, *kb, *vb, *ctx, *x2, *yb, *hb;
    cudaGetSymbolAddress((void**)&xln, g_xln);
    cudaGetSymbolAddress((void**)&qb,  g_q);
    cudaGetSymbolAddress((void**)&kb,  g_k);
    cudaGetSymbolAddress((void**)&vb,  g_v);
    cudaGetSymbolAddress((void**)&ctx, g_ctx);
    cudaGetSymbolAddress((void**)&x2,  g_x2);
    cudaGetSymbolAddress((void**)&yb,  g_y);
    cudaGetSymbolAddress((void**)&hb,  g_h);

    cudaFuncSetAttribute(attn_kernel,
                         cudaFuncAttributeMaxDynamicSharedMemorySize,
                         ATTN_SMEM_BYTES);

    const int M = BB * SS;   // 8192

    // LN1
    ln_kernel<<<M, 256>>>(hidden, ln1g, ln1b, xln);
    // Q, K, V projections
    gemm128<<<dim3(DD/128, M/128), 256>>>(xln, Wq, nullptr, nullptr, qb, M, DD, DD, 0);
    gemm128<<<dim3(DD/128, M/128), 256>>>(xln, Wk, nullptr, nullptr, kb, M, DD, DD, 0);
    gemm128<<<dim3(DD/128, M/128), 256>>>(xln, Wv, nullptr, nullptr, vb, M, DD, DD, 0);
    // Attention
    attn_kernel<<<dim3(SS/64, BB*HH), 256, ATTN_SMEM_BYTES>>>(qb, kb, vb, amask, ctx);
    // Output projection + residual
    gemm128<<<dim3(DD/128, M/128), 256>>>(ctx, Wo, nullptr, hidden, x2, M, DD, DD, 0);
    // LN2
    ln_kernel<<<M, 256>>>(x2, ln2g, ln2b, yb);
    // FFN
    gemm128<<<dim3(FF/128, M/128), 256>>>(yb, W1, b1, nullptr, hb, M, FF, DD, 1);
    gemm128<<<dim3(DD/128, M/128), 256>>>(hb, W2, b2, x2, out, M, DD, FF, 0);
}

// round 3
// speedup vs baseline: 1.7096x; 1.7096x over previous
#include <cuda_runtime.h>
#include <cuda_bf16.h>
#include <math.h>
#include <stdint.h>

#define BB 4
#define SS 2048
#define DD 1024
#define FF 4096
#define HH 16
#define INV_SCALE 0.125f
#define NEGBIG -1e30f
#define MROWS (BB*SS)

// ---------------- scratch ------------------------------------------------------
__device__ float g_xln[BB*SS*DD];
__device__ float g_q  [BB*SS*DD];
__device__ float g_k  [BB*SS*DD];
__device__ float g_v  [BB*SS*DD];
__device__ float g_ctx[BB*SS*DD];
__device__ float g_x2 [BB*SS*DD];
__device__ float g_y  [BB*SS*DD];
__device__ float g_h  [BB*SS*FF];
#define M1 (DD*DD)
// transposed+split weights, bf16 [N,K]
__device__ __nv_bfloat16 g_wT[24*M1];

// ---------------- helpers ------------------------------------------------------
__device__ __forceinline__ uint32_t split_pack(float a, float b, uint32_t& lo) {
    __nv_bfloat16 ha = __float2bfloat16(a), hb = __float2bfloat16(b);
    __nv_bfloat16 la = __float2bfloat16(a - __bfloat162float(ha));
    __nv_bfloat16 lb = __float2bfloat16(b - __bfloat162float(hb));
    lo = (uint32_t)__bfloat16_as_ushort(la) | ((uint32_t)__bfloat16_as_ushort(lb) << 16);
    return (uint32_t)__bfloat16_as_ushort(ha) | ((uint32_t)__bfloat16_as_ushort(hb) << 16);
}

__device__ __forceinline__ void hmma(float* d, uint32_t a0, uint32_t a1,
                                     uint32_t a2, uint32_t a3,
                                     uint32_t b0, uint32_t b1) {
    asm volatile("mma.sync.aligned.m16n8k16.row.col.f32.bf16.bf16.f32 "
                 "{%0,%1,%2,%3}, {%4,%5,%6,%7}, {%8,%9}, {%0,%1,%2,%3};"
                 : "+f"(d[0]), "+f"(d[1]), "+f"(d[2]), "+f"(d[3])
                 : "r"(a0), "r"(a1), "r"(a2), "r"(a3), "r"(b0), "r"(b1));
}

// ---------------- LayerNorm ----------------------------------------------------
__global__ __launch_bounds__(256)
void ln_kernel(const float* __restrict__ x, const float* __restrict__ g,
               const float* __restrict__ b, float* __restrict__ out)
{
    int row = blockIdx.x;
    int tid = threadIdx.x;
    const float* xr = x + (size_t)row * DD;
    float4 v = *reinterpret_cast<const float4*>(xr + tid * 4);
    float s  = v.x + v.y + v.z + v.w;
    float sq = v.x*v.x + v.y*v.y + v.z*v.z + v.w*v.w;
    #pragma unroll
    for (int o = 16; o > 0; o >>= 1) {
        s  += __shfl_xor_sync(0xffffffffu, s,  o);
        sq += __shfl_xor_sync(0xffffffffu, sq, o);
    }
    __shared__ float ws[8], wq[8];
    __shared__ float smean, srstd;
    int wid = tid >> 5, lane = tid & 31;
    if (lane == 0) { ws[wid] = s; wq[wid] = sq; }
    __syncthreads();
    if (tid == 0) {
        float S = 0.f, Q = 0.f;
        #pragma unroll
        for (int i = 0; i < 8; i++) { S += ws[i]; Q += wq[i]; }
        float mean = S * (1.f / DD);
        float var  = fmaxf(Q * (1.f / DD) - mean * mean, 0.f);
        smean = mean;
        srstd = rsqrtf(var + 1e-12f);
    }
    __syncthreads();
    float mean = smean, rstd = srstd;
    float4 gv = *reinterpret_cast<const float4*>(g + tid * 4);
    float4 bv = *reinterpret_cast<const float4*>(b + tid * 4);
    float4 ov;
    ov.x = (v.x - mean) * rstd * gv.x + bv.x;
    ov.y = (v.y - mean) * rstd * gv.y + bv.y;
    ov.z = (v.z - mean) * rstd * gv.z + bv.z;
    ov.w = (v.w - mean) * rstd * gv.w + bv.w;
    *reinterpret_cast<float4*>(out + (size_t)row * DD + tid * 4) = ov;
}

// ---------------- weight transpose + bf16 split: W[K,N] -> hiT/loT [N,K] -------
__global__ __launch_bounds__(256)
void transsplit(const float* __restrict__ W, __nv_bfloat16* __restrict__ hiT,
                __nv_bfloat16* __restrict__ loT, int K, int N)
{
    __shared__ float tile[32][33];
    int n0 = blockIdx.x * 32, k0 = blockIdx.y * 32;
    int tx = threadIdx.x & 31, ty = threadIdx.x >> 5;
    for (int j = ty; j < 32; j += 8)
        tile[j][tx] = W[(size_t)(k0 + j) * N + n0 + tx];
    __syncthreads();
    for (int j = ty; j < 32; j += 8) {
        float x = tile[tx][j];   // W[k0+tx][n0+j]
        __nv_bfloat16 h = __float2bfloat16(x);
        __nv_bfloat16 l = __float2bfloat16(x - __bfloat162float(h));
        size_t o = (size_t)(n0 + j) * K + k0 + tx;
        hiT[o] = h; loT[o] = l;
    }
}

// ---------------- bf16x3 HMMA GEMM: C[M,N] = A[M,K] @ B^T (B as [N,K] hi/lo) ---
// CTA tile 128x128, BK=32, 8 warps (4 M x 2 N), warp tile 32x64.
#define ASTRIDE 40                          // halves per SMEM row (conflict-free)
#define TILE_HALVES (128*ASTRIDE)           // per operand per stage
#define STAGE_HALVES (4*TILE_HALVES)        // Ahi, Alo, Bhi, Blo
#define GT_SMEM_BYTES (2*STAGE_HALVES*2)    // double buffered: 81920 B

__global__ __launch_bounds__(256, 1)
void gemm_tc(const float* __restrict__ A,
             const __nv_bfloat16* __restrict__ BhiT,
             const __nv_bfloat16* __restrict__ BloT,
             const float* __restrict__ bias, const float* __restrict__ res,
             float* __restrict__ C, int M, int N, int K, int act)
{
    extern __shared__ uint16_t sh[];
    int tid = threadIdx.x;
    int wid = tid >> 5, lane = tid & 31;
    int g = lane >> 2, tg = lane & 3;
    int warp_m = wid & 3, warp_n = wid >> 2;
    int m0 = blockIdx.y * 128, n0 = blockIdx.x * 128;

    float acc[2][8][4];
    #pragma unroll
    for (int mt = 0; mt < 2; mt++)
        #pragma unroll
        for (int nt = 0; nt < 8; nt++)
            #pragma unroll
            for (int c = 0; c < 4; c++) acc[mt][nt][c] = 0.f;

    // per-thread load coordinates
    // A: 1024 float4 per stage -> 4 per thread
    int af[4], ar[4], ac[4];
    #pragma unroll
    for (int u = 0; u < 4; u++) {
        int f = tid + u * 256;
        ar[u] = f >> 3;             // row 0..127
        ac[u] = (f & 7) << 2;       // col 0..28
        af[u] = f;
    }
    // B: 1024 uint4 per stage (512 hi + 512 lo) -> 4 per thread
    int bh_[4], br[4], bc[4];
    #pragma unroll
    for (int u = 0; u < 4; u++) {
        int f = tid + u * 256;
        bh_[u] = f >> 9;            // 0 = hi, 1 = lo
        int fr = f & 511;
        br[u] = fr >> 2;            // row 0..127
        bc[u] = (fr & 3) << 3;      // col 0,8,16,24
    }

    const int T = K >> 5;

    // ---- fill stage 0 ----
    {
        uint16_t* Ah = sh;
        uint16_t* Al = sh + TILE_HALVES;
        uint16_t* Bh = sh + 2 * TILE_HALVES;
        uint16_t* Bl = sh + 3 * TILE_HALVES;
        #pragma unroll
        for (int u = 0; u < 4; u++) {
            float4 v = *reinterpret_cast<const float4*>(A + (size_t)(m0 + ar[u]) * K + ac[u]);
            uint32_t lo0, lo1;
            uint32_t hi0 = split_pack(v.x, v.y, lo0);
            uint32_t hi1 = split_pack(v.z, v.w, lo1);
            int idx = ar[u] * ASTRIDE + ac[u];
            *reinterpret_cast<uint2*>(Ah + idx) = make_uint2(hi0, hi1);
            *reinterpret_cast<uint2*>(Al + idx) = make_uint2(lo0, lo1);
        }
        #pragma unroll
        for (int u = 0; u < 4; u++) {
            const __nv_bfloat16* src = (bh_[u] ? BloT : BhiT) + (size_t)(n0 + br[u]) * K + bc[u];
            uint4 v = *reinterpret_cast<const uint4*>(src);
            *reinterpret_cast<uint4*>((bh_[u] ? Bl : Bh) + br[u] * ASTRIDE + bc[u]) = v;
        }
    }
    __syncthreads();

    float4 pa[4];
    uint4  pb[4];

    for (int t = 0; t < T; t++) {
        int k0n = (t + 1) << 5;
        bool more = (t + 1 < T);
        if (more) {
            #pragma unroll
            for (int u = 0; u < 4; u++)
                pa[u] = *reinterpret_cast<const float4*>(A + (size_t)(m0 + ar[u]) * K + k0n + ac[u]);
            #pragma unroll
            for (int u = 0; u < 4; u++) {
                const __nv_bfloat16* src = (bh_[u] ? BloT : BhiT)
                                           + (size_t)(n0 + br[u]) * K + k0n + bc[u];
                pb[u] = *reinterpret_cast<const uint4*>(src);
            }
        }

        const uint16_t* Ah = sh + (t & 1) * STAGE_HALVES;
        const uint16_t* Al = Ah + TILE_HALVES;
        const uint16_t* Bh = Ah + 2 * TILE_HALVES;
        const uint16_t* Bl = Ah + 3 * TILE_HALVES;

        #pragma unroll
        for (int ks = 0; ks < 32; ks += 16) {
            uint32_t ahi[2][4], alo[2][4];
            #pragma unroll
            for (int mt = 0; mt < 2; mt++) {
                int row = warp_m * 32 + mt * 16 + g;
                int col = ks + 2 * tg;
                ahi[mt][0] = *reinterpret_cast<const uint32_t*>(Ah + row * ASTRIDE + col);
                ahi[mt][1] = *reinterpret_cast<const uint32_t*>(Ah + (row + 8) * ASTRIDE + col);
                ahi[mt][2] = *reinterpret_cast<const uint32_t*>(Ah + row * ASTRIDE + col + 8);
                ahi[mt][3] = *reinterpret_cast<const uint32_t*>(Ah + (row + 8) * ASTRIDE + col + 8);
                alo[mt][0] = *reinterpret_cast<const uint32_t*>(Al + row * ASTRIDE + col);
                alo[mt][1] = *reinterpret_cast<const uint32_t*>(Al + (row + 8) * ASTRIDE + col);
                alo[mt][2] = *reinterpret_cast<const uint32_t*>(Al + row * ASTRIDE + col + 8);
                alo[mt][3] = *reinterpret_cast<const uint32_t*>(Al + (row + 8) * ASTRIDE + col + 8);
            }
            #pragma unroll
            for (int nt = 0; nt < 8; nt++) {
                int nr = warp_n * 64 + nt * 8 + g;
                int col = ks + 2 * tg;
                uint32_t b0h = *reinterpret_cast<const uint32_t*>(Bh + nr * ASTRIDE + col);
                uint32_t b1h = *reinterpret_cast<const uint32_t*>(Bh + nr * ASTRIDE + col + 8);
                uint32_t b0l = *reinterpret_cast<const uint32_t*>(Bl + nr * ASTRIDE + col);
                uint32_t b1l = *reinterpret_cast<const uint32_t*>(Bl + nr * ASTRIDE + col + 8);
                #pragma unroll
                for (int mt = 0; mt < 2; mt++) {
                    hmma(acc[mt][nt], ahi[mt][0], ahi[mt][1], ahi[mt][2], ahi[mt][3], b0h, b1h);
                    hmma(acc[mt][nt], ahi[mt][0], ahi[mt][1], ahi[mt][2], ahi[mt][3], b0l, b1l);
                    hmma(acc[mt][nt], alo[mt][0], alo[mt][1], alo[mt][2], alo[mt][3], b0h, b1h);
                }
            }
        }

        if (more) {
            uint16_t* nAh = sh + ((t + 1) & 1) * STAGE_HALVES;
            uint16_t* nAl = nAh + TILE_HALVES;
            uint16_t* nBh = nAh + 2 * TILE_HALVES;
            uint16_t* nBl = nAh + 3 * TILE_HALVES;
            #pragma unroll
            for (int u = 0; u < 4; u++) {
                uint32_t lo0, lo1;
                uint32_t hi0 = split_pack(pa[u].x, pa[u].y, lo0);
                uint32_t hi1 = split_pack(pa[u].z, pa[u].w, lo1);
                int idx = ar[u] * ASTRIDE + ac[u];
                *reinterpret_cast<uint2*>(nAh + idx) = make_uint2(hi0, hi1);
                *reinterpret_cast<uint2*>(nAl + idx) = make_uint2(lo0, lo1);
            }
            #pragma unroll
            for (int u = 0; u < 4; u++)
                *reinterpret_cast<uint4*>((bh_[u] ? nBl : nBh) + br[u] * ASTRIDE + bc[u]) = pb[u];
            __syncthreads();
        }
    }

    // ---- epilogue: direct stores from fragments ----
    #pragma unroll
    for (int mt = 0; mt < 2; mt++) {
        #pragma unroll
        for (int nt = 0; nt < 8; nt++) {
            int row = m0 + warp_m * 32 + mt * 16 + g;
            int col = n0 + warp_n * 64 + nt * 8 + 2 * tg;
            #pragma unroll
            for (int half = 0; half < 2; half++) {
                int r = row + half * 8;
                float v0 = acc[mt][nt][half * 2 + 0];
                float v1 = acc[mt][nt][half * 2 + 1];
                if (bias) { v0 += bias[col]; v1 += bias[col + 1]; }
                if (act) {
                    v0 = v0 / (1.f + __expf(-v0));
                    v1 = v1 / (1.f + __expf(-v1));
                }
                size_t o = (size_t)r * N + col;
                if (res) {
                    float2 rv = *reinterpret_cast<const float2*>(res + o);
                    v0 += rv.x; v1 += rv.y;
                }
                *reinterpret_cast<float2*>(C + o) = make_float2(v0, v1);
            }
        }
    }
}

// ---------------- Flash attention, fp32, causal + key pad mask -----------------
#define ATTN_SMEM_FLOATS (4*64*64 + 64*16 + 4*64)
#define ATTN_SMEM_BYTES  (ATTN_SMEM_FLOATS * 4)

__global__ __launch_bounds__(256)
void attn_kernel(const float* __restrict__ q, const float* __restrict__ k,
                 const float* __restrict__ v, const int* __restrict__ amask,
                 float* __restrict__ ctx)
{
    extern __shared__ float sm[];
    float (*Qs)[64]  = (float(*)[64])(sm);
    float (*Ks)[64]  = (float(*)[64])(sm + 4096);
    float (*Vs)[64]  = (float(*)[64])(sm + 8192);
    float (*Ps)[64]  = (float(*)[64])(sm + 12288);
    float (*red)[16] = (float(*)[16])(sm + 16384);
    float* mrow = sm + 16384 + 1024;
    float* lrow = mrow + 64;
    float* arow = lrow + 64;
    float* koff = arow + 64;

    int tid = threadIdx.x;
    int bh  = blockIdx.y;
    int b   = bh >> 4, h = bh & 15;
    int q0  = blockIdx.x * 64;
    int tr  = tid >> 4, tc = tid & 15;
    const size_t base = ((size_t)b * SS) * DD + (size_t)h * 64;

    #pragma unroll
    for (int t = 0; t < 4; t++) {
        int f  = tid + t * 256;
        int r  = f >> 4;
        int c4 = (f & 15) << 2;
        float4 qv = *reinterpret_cast<const float4*>(q + base + (size_t)(q0 + r) * DD + c4);
        Qs[c4 + 0][r] = qv.x; Qs[c4 + 1][r] = qv.y;
        Qs[c4 + 2][r] = qv.z; Qs[c4 + 3][r] = qv.w;
    }
    if (tid < 64) { mrow[tid] = NEGBIG; lrow[tid] = 0.f; }

    float acc[4][4];
    #pragma unroll
    for (int i = 0; i < 4; i++)
        #pragma unroll
        for (int j = 0; j < 4; j++) acc[i][j] = 0.f;

    for (int kt = 0; kt <= blockIdx.x; kt++) {
        int k0 = kt * 64;
        __syncthreads();

        #pragma unroll
        for (int t = 0; t < 4; t++) {
            int f  = tid + t * 256;
            int r  = f >> 4;
            int c4 = (f & 15) << 2;
            float4 kv = *reinterpret_cast<const float4*>(k + base + (size_t)(k0 + r) * DD + c4);
            Ks[c4 + 0][r] = kv.x; Ks[c4 + 1][r] = kv.y;
            Ks[c4 + 2][r] = kv.z; Ks[c4 + 3][r] = kv.w;
            float4 vv = *reinterpret_cast<const float4*>(v + base + (size_t)(k0 + r) * DD + c4);
            *reinterpret_cast<float4*>(&Vs[r][c4]) = vv;
        }
        if (tid < 64)
            koff[tid] = (amask[b * SS + k0 + tid] == 1) ? 0.f : NEGBIG;
        __syncthreads();

        float s[4][4];
        #pragma unroll
        for (int i = 0; i < 4; i++)
            #pragma unroll
            for (int j = 0; j < 4; j++) s[i][j] = 0.f;
        #pragma unroll 8
        for (int kk = 0; kk < 64; kk++) {
            float a[4], bq[4];
            #pragma unroll
            for (int i = 0; i < 4; i++) a[i]  = Qs[kk][tr * 4 + i];
            #pragma unroll
            for (int j = 0; j < 4; j++) bq[j] = Ks[kk][tc * 4 + j];
            #pragma unroll
            for (int i = 0; i < 4; i++)
                #pragma unroll
                for (int j = 0; j < 4; j++) s[i][j] += a[i] * bq[j];
        }

        float pmax[4];
        #pragma unroll
        for (int i = 0; i < 4; i++) {
            pmax[i] = NEGBIG;
            int qi = q0 + tr * 4 + i;
            #pragma unroll
            for (int j = 0; j < 4; j++) {
                int kj = k0 + tc * 4 + j;
                float x = s[i][j] * INV_SCALE + koff[tc * 4 + j];
                if (kj > qi) x = NEGBIG;
                s[i][j] = x;
                pmax[i] = fmaxf(pmax[i], x);
            }
        }
        #pragma unroll
        for (int i = 0; i < 4; i++) red[tr * 4 + i][tc] = pmax[i];
        __syncthreads();
        if (tid < 64) {
            float mx = NEGBIG;
            #pragma unroll
            for (int t = 0; t < 16; t++) mx = fmaxf(mx, red[tid][t]);
            float mnew = fmaxf(mrow[tid], mx);
            arow[tid] = __expf(mrow[tid] - mnew);
            mrow[tid] = mnew;
        }
        __syncthreads();

        float psum[4];
        #pragma unroll
        for (int i = 0; i < 4; i++) {
            float mi = mrow[tr * 4 + i];
            psum[i] = 0.f;
            #pragma unroll
            for (int j = 0; j < 4; j++) {
                float p = __expf(s[i][j] - mi);
                Ps[tc * 4 + j][tr * 4 + i] = p;
                psum[i] += p;
            }
        }
        #pragma unroll
        for (int i = 0; i < 4; i++) red[tr * 4 + i][tc] = psum[i];
        __syncthreads();
        if (tid < 64) {
            float sm_ = 0.f;
            #pragma unroll
            for (int t = 0; t < 16; t++) sm_ += red[tid][t];
            lrow[tid] = lrow[tid] * arow[tid] + sm_;
        }

        float al[4];
        #pragma unroll
        for (int i = 0; i < 4; i++) al[i] = arow[tr * 4 + i];
        #pragma unroll
        for (int i = 0; i < 4; i++)
            #pragma unroll
            for (int j = 0; j < 4; j++) acc[i][j] *= al[i];
        #pragma unroll 8
        for (int kk = 0; kk < 64; kk++) {
            float a[4], bq[4];
            #pragma unroll
            for (int i = 0; i < 4; i++) a[i]  = Ps[kk][tr * 4 + i];
            #pragma unroll
            for (int j = 0; j < 4; j++) bq[j] = Vs[kk][tc * 4 + j];
            #pragma unroll
            for (int i = 0; i < 4; i++)
                #pragma unroll
                for (int j = 0; j < 4; j++) acc[i][j] += a[i] * bq[j];
        }
    }
    __syncthreads();

    #pragma unroll
    for (int i = 0; i < 4; i++) {
        float inv = 1.f / lrow[tr * 4 + i];
        float4 ov;
        ov.x = acc[i][0] * inv; ov.y = acc[i][1] * inv;
        ov.z = acc[i][2] * inv; ov.w = acc[i][3] * inv;
        *reinterpret_cast<float4*>(ctx + base + (size_t)(q0 + tr * 4 + i) * DD + tc * 4) = ov;
    }
}

// ---------------- host ---------------------------------------------------------
extern "C" void kernel_launch(void* const* d_in, const int* in_sizes, int n_in,
                              void* d_out, int out_size)
{
    const float* hidden = (const float*)d_in[0];
    const int*   amask  = (const int*)  d_in[1];
    const float* Wq     = (const float*)d_in[2];
    const float* Wk     = (const float*)d_in[3];
    const float* Wv     = (const float*)d_in[4];
    const float* Wo     = (const float*)d_in[5];
    const float* ln1g   = (const float*)d_in[6];
    const float* ln1b   = (const float*)d_in[7];
    const float* W1     = (const float*)d_in[8];
    const float* b1     = (const float*)d_in[9];
    const float* W2     = (const float*)d_in[10];
    const float* b2     = (const float*)d_in[11];
    const float* ln2g   = (const float*)d_in[12];
    const float* ln2b   = (const float*)d_in[13];
    float* out = (float*)d_out;

    float *xln, *qb, *kb, *vb, *ctx, *x2, *yb, *hb;
    __nv_bfloat16* wT;
    cudaGetSymbolAddress((void**)&xln, g_xln);
    cudaGetSymbolAddress((void**)&qb,  g_q);
    cudaGetSymbolAddress((void**)&kb,  g_k);
    cudaGetSymbolAddress((void**)&vb,  g_v);
    cudaGetSymbolAddress((void**)&ctx, g_ctx);
    cudaGetSymbolAddress((void**)&x2,  g_x2);
    cudaGetSymbolAddress((void**)&yb,  g_y);
    cudaGetSymbolAddress((void**)&hb,  g_h);
    cudaGetSymbolAddress((void**)&wT,  g_wT);

    cudaFuncSetAttribute(attn_kernel, cudaFuncAttributeMaxDynamicSharedMemorySize,
                         ATTN_SMEM_BYTES);
    cudaFuncSetAttribute(gemm_tc, cudaFuncAttributeMaxDynamicSharedMemorySize,
                         GT_SMEM_BYTES);

    const int M = MROWS;   // 8192

    // weight transpose + split (bf16 [N,K])
    transsplit<<<dim3(DD/32, DD/32), 256>>>(Wq, wT,        wT + M1,    DD, DD);
    transsplit<<<dim3(DD/32, DD/32), 256>>>(Wk, wT + 2*M1, wT + 3*M1,  DD, DD);
    transsplit<<<dim3(DD/32, DD/32), 256>>>(Wv, wT + 4*M1, wT + 5*M1,  DD, DD);
    transsplit<<<dim3(DD/32, DD/32), 256>>>(Wo, wT + 6*M1, wT + 7*M1,  DD, DD);
    transsplit<<<dim3(FF/32, DD/32), 256>>>(W1, wT + 8*M1, wT + 12*M1, DD, FF);
    transsplit<<<dim3(DD/32, FF/32), 256>>>(W2, wT + 16*M1, wT + 20*M1, FF, DD);

    // LN1
    ln_kernel<<<M, 256>>>(hidden, ln1g, ln1b, xln);
    // QKV projections (HMMA bf16x3)
    gemm_tc<<<dim3(DD/128, M/128), 256, GT_SMEM_BYTES>>>(xln, wT,        wT + M1,   nullptr, nullptr, qb, M, DD, DD, 0);
    gemm_tc<<<dim3(DD/128, M/128), 256, GT_SMEM_BYTES>>>(xln, wT + 2*M1, wT + 3*M1, nullptr, nullptr, kb, M, DD, DD, 0);
    gemm_tc<<<dim3(DD/128, M/128), 256, GT_SMEM_BYTES>>>(xln, wT + 4*M1, wT + 5*M1, nullptr, nullptr, vb, M, DD, DD, 0);
    // Attention
    attn_kernel<<<dim3(SS/64, BB*HH), 256, ATTN_SMEM_BYTES>>>(qb, kb, vb, amask, ctx);
    // Output projection + residual
    gemm_tc<<<dim3(DD/128, M/128), 256, GT_SMEM_BYTES>>>(ctx, wT + 6*M1, wT + 7*M1, nullptr, hidden, x2, M, DD, DD, 0);
    // LN2
    ln_kernel<<<M, 256>>>(x2, ln2g, ln2b, yb);
    // FFN
    gemm_tc<<<dim3(FF/128, M/128), 256, GT_SMEM_BYTES>>>(yb, wT + 8*M1,  wT + 12*M1, b1, nullptr, hb,  M, FF, DD, 1);
    gemm_tc<<<dim3(DD/128, M/128), 256, GT_SMEM_BYTES>>>(hb, wT + 16*M1, wT + 20*M1, b2, x2,      out, M, DD, FF, 0);
}

// round 4
// speedup vs baseline: 2.0976x; 1.2269x over previous
#include <cuda_runtime.h>
#include <cuda_bf16.h>
#include <math.h>
#include <stdint.h>

#define BB 4
#define SS 2048
#define DD 1024
#define FF 4096
#define HH 16
#define QKVD (3*DD)
#define INV_SCALE 0.125f
#define NEGBIG -1e30f
#define MROWS (BB*SS)

// ---------------- scratch ------------------------------------------------------
__device__ float g_xln[BB*SS*DD];
__device__ float g_qkv[BB*SS*QKVD];
__device__ float g_ctx[BB*SS*DD];
__device__ float g_x2 [BB*SS*DD];
__device__ float g_y  [BB*SS*DD];
__device__ float g_h  [BB*SS*FF];
#define M1 (DD*DD)
__device__ __nv_bfloat16 g_wT[24*M1];

// ---------------- helpers ------------------------------------------------------
__device__ __forceinline__ uint32_t split_pack(float a, float b, uint32_t& lo) {
    __nv_bfloat16 ha = __float2bfloat16(a), hb = __float2bfloat16(b);
    __nv_bfloat16 la = __float2bfloat16(a - __bfloat162float(ha));
    __nv_bfloat16 lb = __float2bfloat16(b - __bfloat162float(hb));
    lo = (uint32_t)__bfloat16_as_ushort(la) | ((uint32_t)__bfloat16_as_ushort(lb) << 16);
    return (uint32_t)__bfloat16_as_ushort(ha) | ((uint32_t)__bfloat16_as_ushort(hb) << 16);
}

__device__ __forceinline__ void hmma(float* d, uint32_t a0, uint32_t a1,
                                     uint32_t a2, uint32_t a3,
                                     uint32_t b0, uint32_t b1) {
    asm volatile("mma.sync.aligned.m16n8k16.row.col.f32.bf16.bf16.f32 "
                 "{%0,%1,%2,%3}, {%4,%5,%6,%7}, {%8,%9}, {%0,%1,%2,%3};"
                 : "+f"(d[0]), "+f"(d[1]), "+f"(d[2]), "+f"(d[3])
                 : "r"(a0), "r"(a1), "r"(a2), "r"(a3), "r"(b0), "r"(b1));
}

__device__ __forceinline__ uint32_t s2u(const void* p) {
    return (uint32_t)__cvta_generic_to_shared(p);
}
__device__ __forceinline__ void cp16(uint32_t dst, const void* src) {
    asm volatile("cp.async.ca.shared.global [%0], [%1], 16;" :: "r"(dst), "l"(src));
}
__device__ __forceinline__ void cp_commit() {
    asm volatile("cp.async.commit_group;");
}
__device__ __forceinline__ void cp_wait0() {
    asm volatile("cp.async.wait_group 0;");
}
__device__ __forceinline__ uint32_t lds32(const uint16_t* p) {
    return *reinterpret_cast<const uint32_t*>(p);
}

// ---------------- LayerNorm ----------------------------------------------------
__global__ __launch_bounds__(256)
void ln_kernel(const float* __restrict__ x, const float* __restrict__ g,
               const float* __restrict__ b, float* __restrict__ out)
{
    int row = blockIdx.x;
    int tid = threadIdx.x;
    const float* xr = x + (size_t)row * DD;
    float4 v = *reinterpret_cast<const float4*>(xr + tid * 4);
    float s  = v.x + v.y + v.z + v.w;
    float sq = v.x*v.x + v.y*v.y + v.z*v.z + v.w*v.w;
    #pragma unroll
    for (int o = 16; o > 0; o >>= 1) {
        s  += __shfl_xor_sync(0xffffffffu, s,  o);
        sq += __shfl_xor_sync(0xffffffffu, sq, o);
    }
    __shared__ float ws[8], wq[8];
    __shared__ float smean, srstd;
    int wid = tid >> 5, lane = tid & 31;
    if (lane == 0) { ws[wid] = s; wq[wid] = sq; }
    __syncthreads();
    if (tid == 0) {
        float S = 0.f, Q = 0.f;
        #pragma unroll
        for (int i = 0; i < 8; i++) { S += ws[i]; Q += wq[i]; }
        float mean = S * (1.f / DD);
        float var  = fmaxf(Q * (1.f / DD) - mean * mean, 0.f);
        smean = mean;
        srstd = rsqrtf(var + 1e-12f);
    }
    __syncthreads();
    float mean = smean, rstd = srstd;
    float4 gv = *reinterpret_cast<const float4*>(g + tid * 4);
    float4 bv = *reinterpret_cast<const float4*>(b + tid * 4);
    float4 ov;
    ov.x = (v.x - mean) * rstd * gv.x + bv.x;
    ov.y = (v.y - mean) * rstd * gv.y + bv.y;
    ov.z = (v.z - mean) * rstd * gv.z + bv.z;
    ov.w = (v.w - mean) * rstd * gv.w + bv.w;
    *reinterpret_cast<float4*>(out + (size_t)row * DD + tid * 4) = ov;
}

// ---------------- weight transpose + bf16 split: W[K,N] -> hiT/loT [N,K] -------
__global__ __launch_bounds__(256)
void transsplit(const float* __restrict__ W, __nv_bfloat16* __restrict__ hiT,
                __nv_bfloat16* __restrict__ loT, int K, int N)
{
    __shared__ float tile[32][33];
    int n0 = blockIdx.x * 32, k0 = blockIdx.y * 32;
    int tx = threadIdx.x & 31, ty = threadIdx.x >> 5;
    for (int j = ty; j < 32; j += 8)
        tile[j][tx] = W[(size_t)(k0 + j) * N + n0 + tx];
    __syncthreads();
    for (int j = ty; j < 32; j += 8) {
        float x = tile[tx][j];
        __nv_bfloat16 h = __float2bfloat16(x);
        __nv_bfloat16 l = __float2bfloat16(x - __bfloat162float(h));
        size_t o = (size_t)(n0 + j) * K + k0 + tx;
        hiT[o] = h; loT[o] = l;
    }
}

// ---------------- bf16x3 HMMA GEMM ---------------------------------------------
#define ASTRIDE 40
#define TILE_HALVES (128*ASTRIDE)
#define STAGE_HALVES (4*TILE_HALVES)
#define GT_SMEM_BYTES (2*STAGE_HALVES*2)

__global__ __launch_bounds__(256, 1)
void gemm_tc(const float* __restrict__ A,
             const __nv_bfloat16* __restrict__ BhiT,
             const __nv_bfloat16* __restrict__ BloT,
             const float* __restrict__ bias, const float* __restrict__ res,
             float* __restrict__ C, int M, int N, int K, int act)
{
    extern __shared__ uint16_t sh[];
    int tid = threadIdx.x;
    int wid = tid >> 5, lane = tid & 31;
    int g = lane >> 2, tg = lane & 3;
    int warp_m = wid & 3, warp_n = wid >> 2;
    int m0 = blockIdx.y * 128, n0 = blockIdx.x * 128;

    float acc[2][8][4];
    #pragma unroll
    for (int mt = 0; mt < 2; mt++)
        #pragma unroll
        for (int nt = 0; nt < 8; nt++)
            #pragma unroll
            for (int c = 0; c < 4; c++) acc[mt][nt][c] = 0.f;

    int ar[4], ac[4];
    #pragma unroll
    for (int u = 0; u < 4; u++) {
        int f = tid + u * 256;
        ar[u] = f >> 3;
        ac[u] = (f & 7) << 2;
    }
    int bh_[4], br[4], bc[4];
    #pragma unroll
    for (int u = 0; u < 4; u++) {
        int f = tid + u * 256;
        bh_[u] = f >> 9;
        int fr = f & 511;
        br[u] = fr >> 2;
        bc[u] = (fr & 3) << 3;
    }

    const int T = K >> 5;

    // ---- fill stage 0 ----
    {
        uint16_t* Ah = sh;
        uint16_t* Al = sh + TILE_HALVES;
        uint16_t* Bh = sh + 2 * TILE_HALVES;
        uint16_t* Bl = sh + 3 * TILE_HALVES;
        #pragma unroll
        for (int u = 0; u < 4; u++) {
            const __nv_bfloat16* src = (bh_[u] ? BloT : BhiT) + (size_t)(n0 + br[u]) * K + bc[u];
            cp16(s2u((bh_[u] ? Bl : Bh) + br[u] * ASTRIDE + bc[u]), src);
        }
        cp_commit();
        #pragma unroll
        for (int u = 0; u < 4; u++) {
            float4 v = *reinterpret_cast<const float4*>(A + (size_t)(m0 + ar[u]) * K + ac[u]);
            uint32_t lo0, lo1;
            uint32_t hi0 = split_pack(v.x, v.y, lo0);
            uint32_t hi1 = split_pack(v.z, v.w, lo1);
            int idx = ar[u] * ASTRIDE + ac[u];
            *reinterpret_cast<uint2*>(Ah + idx) = make_uint2(hi0, hi1);
            *reinterpret_cast<uint2*>(Al + idx) = make_uint2(lo0, lo1);
        }
        cp_wait0();
    }
    __syncthreads();

    float4 pa[4];

    for (int t = 0; t < T; t++) {
        int k0n = (t + 1) << 5;
        bool more = (t + 1 < T);
        uint16_t* nSt = sh + ((t + 1) & 1) * STAGE_HALVES;
        if (more) {
            #pragma unroll
            for (int u = 0; u < 4; u++)
                pa[u] = *reinterpret_cast<const float4*>(A + (size_t)(m0 + ar[u]) * K + k0n + ac[u]);
            #pragma unroll
            for (int u = 0; u < 4; u++) {
                const __nv_bfloat16* src = (bh_[u] ? BloT : BhiT)
                                           + (size_t)(n0 + br[u]) * K + k0n + bc[u];
                uint16_t* dst = nSt + (2 + bh_[u]) * TILE_HALVES + br[u] * ASTRIDE + bc[u];
                cp16(s2u(dst), src);
            }
            cp_commit();
        }

        const uint16_t* Ah = sh + (t & 1) * STAGE_HALVES;
        const uint16_t* Al = Ah + TILE_HALVES;
        const uint16_t* Bh = Ah + 2 * TILE_HALVES;
        const uint16_t* Bl = Ah + 3 * TILE_HALVES;

        #pragma unroll
        for (int ks = 0; ks < 32; ks += 16) {
            uint32_t ahi[2][4], alo[2][4];
            #pragma unroll
            for (int mt = 0; mt < 2; mt++) {
                int row = warp_m * 32 + mt * 16 + g;
                int col = ks + 2 * tg;
                ahi[mt][0] = lds32(Ah + row * ASTRIDE + col);
                ahi[mt][1] = lds32(Ah + (row + 8) * ASTRIDE + col);
                ahi[mt][2] = lds32(Ah + row * ASTRIDE + col + 8);
                ahi[mt][3] = lds32(Ah + (row + 8) * ASTRIDE + col + 8);
                alo[mt][0] = lds32(Al + row * ASTRIDE + col);
                alo[mt][1] = lds32(Al + (row + 8) * ASTRIDE + col);
                alo[mt][2] = lds32(Al + row * ASTRIDE + col + 8);
                alo[mt][3] = lds32(Al + (row + 8) * ASTRIDE + col + 8);
            }
            #pragma unroll
            for (int nt = 0; nt < 8; nt++) {
                int nr = warp_n * 64 + nt * 8 + g;
                int col = ks + 2 * tg;
                uint32_t b0h = lds32(Bh + nr * ASTRIDE + col);
                uint32_t b1h = lds32(Bh + nr * ASTRIDE + col + 8);
                uint32_t b0l = lds32(Bl + nr * ASTRIDE + col);
                uint32_t b1l = lds32(Bl + nr * ASTRIDE + col + 8);
                #pragma unroll
                for (int mt = 0; mt < 2; mt++) {
                    hmma(acc[mt][nt], ahi[mt][0], ahi[mt][1], ahi[mt][2], ahi[mt][3], b0h, b1h);
                    hmma(acc[mt][nt], ahi[mt][0], ahi[mt][1], ahi[mt][2], ahi[mt][3], b0l, b1l);
                    hmma(acc[mt][nt], alo[mt][0], alo[mt][1], alo[mt][2], alo[mt][3], b0h, b1h);
                }
            }
        }

        if (more) {
            uint16_t* nAh = nSt;
            uint16_t* nAl = nSt + TILE_HALVES;
            #pragma unroll
            for (int u = 0; u < 4; u++) {
                uint32_t lo0, lo1;
                uint32_t hi0 = split_pack(pa[u].x, pa[u].y, lo0);
                uint32_t hi1 = split_pack(pa[u].z, pa[u].w, lo1);
                int idx = ar[u] * ASTRIDE + ac[u];
                *reinterpret_cast<uint2*>(nAh + idx) = make_uint2(hi0, hi1);
                *reinterpret_cast<uint2*>(nAl + idx) = make_uint2(lo0, lo1);
            }
            cp_wait0();
            __syncthreads();
        }
    }

    // ---- epilogue ----
    #pragma unroll
    for (int mt = 0; mt < 2; mt++) {
        #pragma unroll
        for (int nt = 0; nt < 8; nt++) {
            int row = m0 + warp_m * 32 + mt * 16 + g;
            int col = n0 + warp_n * 64 + nt * 8 + 2 * tg;
            #pragma unroll
            for (int half = 0; half < 2; half++) {
                int r = row + half * 8;
                float v0 = acc[mt][nt][half * 2 + 0];
                float v1 = acc[mt][nt][half * 2 + 1];
                if (bias) { v0 += bias[col]; v1 += bias[col + 1]; }
                if (act) {
                    v0 = v0 / (1.f + __expf(-v0));
                    v1 = v1 / (1.f + __expf(-v1));
                }
                size_t o = (size_t)r * N + col;
                if (res) {
                    float2 rv = *reinterpret_cast<const float2*>(res + o);
                    v0 += rv.x; v1 += rv.y;
                }
                *reinterpret_cast<float2*>(C + o) = make_float2(v0, v1);
            }
        }
    }
}

// ---------------- tensor-core flash attention ----------------------------------
// 64 q-rows per CTA, 128 threads (4 warps, 16 rows each), bf16x3 HMMA.
#define AT_STRIDE 72
#define AT_SZ (64*AT_STRIDE)
#define AT_SMEM_BYTES (6*AT_SZ*2 + 64*4)

__global__ __launch_bounds__(128)
void attn_tc(const float* __restrict__ qkv, const int* __restrict__ amask,
             float* __restrict__ ctx)
{
    extern __shared__ uint16_t ash[];
    uint16_t* Qh = ash;
    uint16_t* Ql = ash + AT_SZ;
    uint16_t* Kh = ash + 2*AT_SZ;
    uint16_t* Kl = ash + 3*AT_SZ;
    uint16_t* Vh = ash + 4*AT_SZ;
    uint16_t* Vl = ash + 5*AT_SZ;
    float* koff = reinterpret_cast<float*>(ash + 6*AT_SZ);

    int tid = threadIdx.x;
    int lane = tid & 31, w = tid >> 5;
    int g = lane >> 2, tg = lane & 3;
    int bh = blockIdx.y;
    int b = bh >> 4, h = bh & 15;
    int qt = gridDim.x - 1 - blockIdx.x;      // heavy blocks first
    int q0 = qt * 64;
    const size_t rowbase = (size_t)b * SS;
    const int hoff = h * 64;

    // ---- load Q tile, split to hi/lo ----
    #pragma unroll
    for (int u = 0; u < 8; u++) {
        int f = tid + u * 128;
        int r = f >> 4;
        int c4 = (f & 15) << 2;
        float4 qv = *reinterpret_cast<const float4*>(
            qkv + (rowbase + q0 + r) * QKVD + hoff + c4);
        uint32_t lo0, lo1;
        uint32_t hi0 = split_pack(qv.x, qv.y, lo0);
        uint32_t hi1 = split_pack(qv.z, qv.w, lo1);
        int idx = r * AT_STRIDE + c4;
        *reinterpret_cast<uint2*>(Qh + idx) = make_uint2(hi0, hi1);
        *reinterpret_cast<uint2*>(Ql + idx) = make_uint2(lo0, lo1);
    }
    __syncthreads();

    // ---- Q fragments into registers ----
    uint32_t qfh[4][4], qfl[4][4];
    int r0 = w * 16 + g;
    #pragma unroll
    for (int kt = 0; kt < 4; kt++) {
        int base = 16 * kt + 2 * tg;
        qfh[kt][0] = lds32(Qh + r0 * AT_STRIDE + base);
        qfh[kt][1] = lds32(Qh + (r0 + 8) * AT_STRIDE + base);
        qfh[kt][2] = lds32(Qh + r0 * AT_STRIDE + base + 8);
        qfh[kt][3] = lds32(Qh + (r0 + 8) * AT_STRIDE + base + 8);
        qfl[kt][0] = lds32(Ql + r0 * AT_STRIDE + base);
        qfl[kt][1] = lds32(Ql + (r0 + 8) * AT_STRIDE + base);
        qfl[kt][2] = lds32(Ql + r0 * AT_STRIDE + base + 8);
        qfl[kt][3] = lds32(Ql + (r0 + 8) * AT_STRIDE + base + 8);
    }

    float o[8][4];
    #pragma unroll
    for (int nt = 0; nt < 8; nt++)
        #pragma unroll
        for (int c = 0; c < 4; c++) o[nt][c] = 0.f;
    float m0v = NEGBIG, m1v = NEGBIG, l0 = 0.f, l1 = 0.f;
    int r0g = q0 + r0, r1g = r0g + 8;

    for (int kt_g = 0; kt_g <= qt; kt_g++) {
        int k0 = kt_g * 64;
        __syncthreads();   // prior tile fully consumed

        // ---- load K (natural) and V (transposed), split hi/lo ----
        #pragma unroll
        for (int u = 0; u < 8; u++) {
            int f = tid + u * 128;
            int r = f >> 4;
            int c4 = (f & 15) << 2;
            const float* kp = qkv + (rowbase + k0 + r) * QKVD + DD + hoff + c4;
            float4 kv = *reinterpret_cast<const float4*>(kp);
            uint32_t lo0, lo1;
            uint32_t hi0 = split_pack(kv.x, kv.y, lo0);
            uint32_t hi1 = split_pack(kv.z, kv.w, lo1);
            int idx = r * AT_STRIDE + c4;
            *reinterpret_cast<uint2*>(Kh + idx) = make_uint2(hi0, hi1);
            *reinterpret_cast<uint2*>(Kl + idx) = make_uint2(lo0, lo1);
            const float* vp = qkv + (rowbase + k0 + r) * QKVD + 2*DD + hoff + c4;
            float4 vv = *reinterpret_cast<const float4*>(vp);
            float ve[4] = {vv.x, vv.y, vv.z, vv.w};
            #pragma unroll
            for (int j = 0; j < 4; j++) {
                __nv_bfloat16 hb = __float2bfloat16(ve[j]);
                __nv_bfloat16 lb = __float2bfloat16(ve[j] - __bfloat162float(hb));
                Vh[(c4 + j) * AT_STRIDE + r] = __bfloat16_as_ushort(hb);
                Vl[(c4 + j) * AT_STRIDE + r] = __bfloat16_as_ushort(lb);
            }
        }
        if (tid < 64)
            koff[tid] = (amask[b * SS + k0 + tid] == 1) ? 0.f : NEGBIG;
        __syncthreads();

        // ---- S = Q K^T (bf16x3) ----
        float s[8][4];
        #pragma unroll
        for (int nt = 0; nt < 8; nt++)
            #pragma unroll
            for (int c = 0; c < 4; c++) s[nt][c] = 0.f;
        #pragma unroll
        for (int kt = 0; kt < 4; kt++) {
            int base = 16 * kt + 2 * tg;
            #pragma unroll
            for (int nt = 0; nt < 8; nt++) {
                const uint16_t* kb = Kh + (8 * nt + g) * AT_STRIDE + base;
                const uint16_t* kbl = Kl + (8 * nt + g) * AT_STRIDE + base;
                uint32_t b0h = lds32(kb), b1h = lds32(kb + 8);
                uint32_t b0l = lds32(kbl), b1l = lds32(kbl + 8);
                hmma(s[nt], qfh[kt][0], qfh[kt][1], qfh[kt][2], qfh[kt][3], b0h, b1h);
                hmma(s[nt], qfh[kt][0], qfh[kt][1], qfh[kt][2], qfh[kt][3], b0l, b1l);
                hmma(s[nt], qfl[kt][0], qfl[kt][1], qfl[kt][2], qfl[kt][3], b0h, b1h);
            }
        }

        // ---- scale + mask + row max ----
        bool diag = (kt_g == qt);
        float mx0 = NEGBIG, mx1 = NEGBIG;
        #pragma unroll
        for (int nt = 0; nt < 8; nt++) {
            int c0 = 8 * nt + 2 * tg;
            float kf0 = koff[c0], kf1 = koff[c0 + 1];
            float v0 = s[nt][0] * INV_SCALE + kf0;
            float v1 = s[nt][1] * INV_SCALE + kf1;
            float v2 = s[nt][2] * INV_SCALE + kf0;
            float v3 = s[nt][3] * INV_SCALE + kf1;
            if (diag) {
                if (k0 + c0     > r0g) v0 = NEGBIG;
                if (k0 + c0 + 1 > r0g) v1 = NEGBIG;
                if (k0 + c0     > r1g) v2 = NEGBIG;
                if (k0 + c0 + 1 > r1g) v3 = NEGBIG;
            }
            s[nt][0] = v0; s[nt][1] = v1; s[nt][2] = v2; s[nt][3] = v3;
            mx0 = fmaxf(mx0, fmaxf(v0, v1));
            mx1 = fmaxf(mx1, fmaxf(v2, v3));
        }
        mx0 = fmaxf(mx0, __shfl_xor_sync(0xffffffffu, mx0, 1));
        mx0 = fmaxf(mx0, __shfl_xor_sync(0xffffffffu, mx0, 2));
        mx1 = fmaxf(mx1, __shfl_xor_sync(0xffffffffu, mx1, 1));
        mx1 = fmaxf(mx1, __shfl_xor_sync(0xffffffffu, mx1, 2));

        float mn0 = fmaxf(m0v, mx0), mn1 = fmaxf(m1v, mx1);
        float al0 = __expf(m0v - mn0), al1 = __expf(m1v - mn1);
        m0v = mn0; m1v = mn1;
        l0 *= al0; l1 *= al1;

        // ---- P = exp(S - m), per-lane partial sums ----
        #pragma unroll
        for (int nt = 0; nt < 8; nt++) {
            float p0 = __expf(s[nt][0] - m0v);
            float p1 = __expf(s[nt][1] - m0v);
            float p2 = __expf(s[nt][2] - m1v);
            float p3 = __expf(s[nt][3] - m1v);
            s[nt][0] = p0; s[nt][1] = p1; s[nt][2] = p2; s[nt][3] = p3;
            l0 += p0 + p1; l1 += p2 + p3;
        }
        #pragma unroll
        for (int nt = 0; nt < 8; nt++) {
            o[nt][0] *= al0; o[nt][1] *= al0;
            o[nt][2] *= al1; o[nt][3] *= al1;
        }

        // ---- O += P V (bf16x3), P fragments straight from registers ----
        #pragma unroll
        for (int ktP = 0; ktP < 4; ktP++) {
            int ntA = 2 * ktP, ntB = ntA + 1;
            uint32_t a0l, a1l, a2l, a3l;
            uint32_t a0h = split_pack(s[ntA][0], s[ntA][1], a0l);
            uint32_t a1h = split_pack(s[ntA][2], s[ntA][3], a1l);
            uint32_t a2h = split_pack(s[ntB][0], s[ntB][1], a2l);
            uint32_t a3h = split_pack(s[ntB][2], s[ntB][3], a3l);
            int base = 16 * ktP + 2 * tg;
            #pragma unroll
            for (int nt2 = 0; nt2 < 8; nt2++) {
                const uint16_t* vb = Vh + (8 * nt2 + g) * AT_STRIDE + base;
                const uint16_t* vbl = Vl + (8 * nt2 + g) * AT_STRIDE + base;
                uint32_t b0h = lds32(vb), b1h = lds32(vb + 8);
                uint32_t b0l = lds32(vbl), b1l = lds32(vbl + 8);
                hmma(o[nt2], a0h, a1h, a2h, a3h, b0h, b1h);
                hmma(o[nt2], a0l, a1l, a2l, a3l, b0h, b1h);
                hmma(o[nt2], a0h, a1h, a2h, a3h, b0l, b1l);
            }
        }
    }

    // ---- finalize ----
    l0 += __shfl_xor_sync(0xffffffffu, l0, 1);
    l0 += __shfl_xor_sync(0xffffffffu, l0, 2);
    l1 += __shfl_xor_sync(0xffffffffu, l1, 1);
    l1 += __shfl_xor_sync(0xffffffffu, l1, 2);
    float inv0 = 1.f / l0, inv1 = 1.f / l1;

    #pragma unroll
    for (int nt2 = 0; nt2 < 8; nt2++) {
        int col = hoff + 8 * nt2 + 2 * tg;
        *reinterpret_cast<float2*>(ctx + (rowbase + r0g) * DD + col) =
            make_float2(o[nt2][0] * inv0, o[nt2][1] * inv0);
        *reinterpret_cast<float2*>(ctx + (rowbase + r1g) * DD + col) =
            make_float2(o[nt2][2] * inv1, o[nt2][3] * inv1);
    }
}

// ---------------- host ---------------------------------------------------------
extern "C" void kernel_launch(void* const* d_in, const int* in_sizes, int n_in,
                              void* d_out, int out_size)
{
    const float* hidden = (const float*)d_in[0];
    const int*   amask  = (const int*)  d_in[1];
    const float* Wq     = (const float*)d_in[2];
    const float* Wk     = (const float*)d_in[3];
    const float* Wv     = (const float*)d_in[4];
    const float* Wo     = (const float*)d_in[5];
    const float* ln1g   = (const float*)d_in[6];
    const float* ln1b   = (const float*)d_in[7];
    const float* W1     = (const float*)d_in[8];
    const float* b1     = (const float*)d_in[9];
    const float* W2     = (const float*)d_in[10];
    const float* b2     = (const float*)d_in[11];
    const float* ln2g   = (const float*)d_in[12];
    const float* ln2b   = (const float*)d_in[13];
    float* out = (float*)d_out;

    float *xln, *qkv, *ctx, *x2, *yb, *hb;
    __nv_bfloat16* wT;
    cudaGetSymbolAddress((void**)&xln, g_xln);
    cudaGetSymbolAddress((void**)&qkv, g_qkv);
    cudaGetSymbolAddress((void**)&ctx, g_ctx);
    cudaGetSymbolAddress((void**)&x2,  g_x2);
    cudaGetSymbolAddress((void**)&yb,  g_y);
    cudaGetSymbolAddress((void**)&hb,  g_h);
    cudaGetSymbolAddress((void**)&wT,  g_wT);

    cudaFuncSetAttribute(attn_tc, cudaFuncAttributeMaxDynamicSharedMemorySize,
                         AT_SMEM_BYTES);
    cudaFuncSetAttribute(gemm_tc, cudaFuncAttributeMaxDynamicSharedMemorySize,
                         GT_SMEM_BYTES);

    const int M = MROWS;   // 8192

    // packed QKV weights: hi rows [Wq;Wk;Wv] at 0..3M1, lo at 3M1..6M1
    transsplit<<<dim3(DD/32, DD/32), 256>>>(Wq, wT,          wT + 3*M1,  DD, DD);
    transsplit<<<dim3(DD/32, DD/32), 256>>>(Wk, wT + M1,     wT + 4*M1,  DD, DD);
    transsplit<<<dim3(DD/32, DD/32), 256>>>(Wv, wT + 2*M1,   wT + 5*M1,  DD, DD);
    transsplit<<<dim3(DD/32, DD/32), 256>>>(Wo, wT + 6*M1,   wT + 7*M1,  DD, DD);
    transsplit<<<dim3(FF/32, DD/32), 256>>>(W1, wT + 8*M1,   wT + 12*M1, DD, FF);
    transsplit<<<dim3(DD/32, FF/32), 256>>>(W2, wT + 16*M1,  wT + 20*M1, FF, DD);

    // LN1
    ln_kernel<<<M, 256>>>(hidden, ln1g, ln1b, xln);
    // fused QKV projection
    gemm_tc<<<dim3(QKVD/128, M/128), 256, GT_SMEM_BYTES>>>(
        xln, wT, wT + 3*M1, nullptr, nullptr, qkv, M, QKVD, DD, 0);
    // attention (tensor core)
    attn_tc<<<dim3(SS/64, BB*HH), 128, AT_SMEM_BYTES>>>(qkv, amask, ctx);
    // output projection + residual
    gemm_tc<<<dim3(DD/128, M/128), 256, GT_SMEM_BYTES>>>(
        ctx, wT + 6*M1, wT + 7*M1, nullptr, hidden, x2, M, DD, DD, 0);
    // LN2
    ln_kernel<<<M, 256>>>(x2, ln2g, ln2b, yb);
    // FFN
    gemm_tc<<<dim3(FF/128, M/128), 256, GT_SMEM_BYTES>>>(
        yb, wT + 8*M1, wT + 12*M1, b1, nullptr, hb, M, FF, DD, 1);
    gemm_tc<<<dim3(DD/128, M/128), 256, GT_SMEM_BYTES>>>(
        hb, wT + 16*M1, wT + 20*M1, b2, x2, out, M, DD, FF, 0);
}

// round 5
// speedup vs baseline: 2.6118x; 1.2451x over previous
#include <cuda_runtime.h>
#include <cuda_bf16.h>
#include <math.h>
#include <stdint.h>

#define BB 4
#define SS 2048
#define DD 1024
#define FF 4096
#define HH 16
#define QKVD (3*DD)
#define INV_SCALE 0.125f
#define NEGBIG -1e30f
#define MROWS (BB*SS)
#define M1 (DD*DD)

// ---------------- scratch: split bf16 activation planes ------------------------
__device__ __nv_bfloat16 g_xh [MROWS*DD];
__device__ __nv_bfloat16 g_xl [MROWS*DD];
__device__ __nv_bfloat16 g_qh [MROWS*QKVD];
__device__ __nv_bfloat16 g_ql [MROWS*QKVD];
__device__ __nv_bfloat16 g_ch [MROWS*DD];
__device__ __nv_bfloat16 g_cl [MROWS*DD];
__device__ float         g_x2 [MROWS*DD];
__device__ __nv_bfloat16 g_yh [MROWS*DD];
__device__ __nv_bfloat16 g_yl [MROWS*DD];
__device__ __nv_bfloat16 g_hh [MROWS*FF];
__device__ __nv_bfloat16 g_hl [MROWS*FF];
__device__ __nv_bfloat16 g_wT [24*M1];

// ---------------- helpers ------------------------------------------------------
__device__ __forceinline__ uint32_t split_pack(float a, float b, uint32_t& lo) {
    __nv_bfloat16 ha = __float2bfloat16(a), hb = __float2bfloat16(b);
    __nv_bfloat16 la = __float2bfloat16(a - __bfloat162float(ha));
    __nv_bfloat16 lb = __float2bfloat16(b - __bfloat162float(hb));
    lo = (uint32_t)__bfloat16_as_ushort(la) | ((uint32_t)__bfloat16_as_ushort(lb) << 16);
    return (uint32_t)__bfloat16_as_ushort(ha) | ((uint32_t)__bfloat16_as_ushort(hb) << 16);
}
__device__ __forceinline__ void hmma(float* d, uint32_t a0, uint32_t a1,
                                     uint32_t a2, uint32_t a3,
                                     uint32_t b0, uint32_t b1) {
    asm volatile("mma.sync.aligned.m16n8k16.row.col.f32.bf16.bf16.f32 "
                 "{%0,%1,%2,%3}, {%4,%5,%6,%7}, {%8,%9}, {%0,%1,%2,%3};"
                 : "+f"(d[0]), "+f"(d[1]), "+f"(d[2]), "+f"(d[3])
                 : "r"(a0), "r"(a1), "r"(a2), "r"(a3), "r"(b0), "r"(b1));
}
__device__ __forceinline__ uint32_t s2u(const void* p) {
    return (uint32_t)__cvta_generic_to_shared(p);
}
__device__ __forceinline__ void cp16(uint32_t dst, const void* src) {
    asm volatile("cp.async.ca.shared.global [%0], [%1], 16;" :: "r"(dst), "l"(src));
}
__device__ __forceinline__ void cp_commit() { asm volatile("cp.async.commit_group;"); }
__device__ __forceinline__ void cp_wait0()  { asm volatile("cp.async.wait_group 0;"); }
__device__ __forceinline__ void cp_wait1()  { asm volatile("cp.async.wait_group 1;"); }
__device__ __forceinline__ void cp_wait2()  { asm volatile("cp.async.wait_group 2;"); }
__device__ __forceinline__ void ldm4(uint32_t addr, uint32_t& r0, uint32_t& r1,
                                     uint32_t& r2, uint32_t& r3) {
    asm volatile("ldmatrix.sync.aligned.m8n8.x4.shared.b16 {%0,%1,%2,%3}, [%4];"
                 : "=r"(r0), "=r"(r1), "=r"(r2), "=r"(r3) : "r"(addr));
}
__device__ __forceinline__ void ldm4t(uint32_t addr, uint32_t& r0, uint32_t& r1,
                                      uint32_t& r2, uint32_t& r3) {
    asm volatile("ldmatrix.sync.aligned.m8n8.x4.trans.shared.b16 {%0,%1,%2,%3}, [%4];"
                 : "=r"(r0), "=r"(r1), "=r"(r2), "=r"(r3) : "r"(addr));
}

// ---------------- LayerNorm with split bf16 output -----------------------------
__global__ __launch_bounds__(256)
void ln_split(const float* __restrict__ x, const float* __restrict__ g,
              const float* __restrict__ b, __nv_bfloat16* __restrict__ outH,
              __nv_bfloat16* __restrict__ outL)
{
    int row = blockIdx.x;
    int tid = threadIdx.x;
    const float* xr = x + (size_t)row * DD;
    float4 v = *reinterpret_cast<const float4*>(xr + tid * 4);
    float s  = v.x + v.y + v.z + v.w;
    float sq = v.x*v.x + v.y*v.y + v.z*v.z + v.w*v.w;
    #pragma unroll
    for (int o = 16; o > 0; o >>= 1) {
        s  += __shfl_xor_sync(0xffffffffu, s,  o);
        sq += __shfl_xor_sync(0xffffffffu, sq, o);
    }
    __shared__ float ws[8], wq[8];
    __shared__ float smean, srstd;
    int wid = tid >> 5, lane = tid & 31;
    if (lane == 0) { ws[wid] = s; wq[wid] = sq; }
    __syncthreads();
    if (tid == 0) {
        float S = 0.f, Q = 0.f;
        #pragma unroll
        for (int i = 0; i < 8; i++) { S += ws[i]; Q += wq[i]; }
        float mean = S * (1.f / DD);
        float var  = fmaxf(Q * (1.f / DD) - mean * mean, 0.f);
        smean = mean;
        srstd = rsqrtf(var + 1e-12f);
    }
    __syncthreads();
    float mean = smean, rstd = srstd;
    float4 gv = *reinterpret_cast<const float4*>(g + tid * 4);
    float4 bv = *reinterpret_cast<const float4*>(b + tid * 4);
    float o0 = (v.x - mean) * rstd * gv.x + bv.x;
    float o1 = (v.y - mean) * rstd * gv.y + bv.y;
    float o2 = (v.z - mean) * rstd * gv.z + bv.z;
    float o3 = (v.w - mean) * rstd * gv.w + bv.w;
    uint32_t l0, l1;
    uint32_t h0 = split_pack(o0, o1, l0);
    uint32_t h1 = split_pack(o2, o3, l1);
    size_t o = (size_t)row * DD + tid * 4;
    *reinterpret_cast<uint2*>(outH + o) = make_uint2(h0, h1);
    *reinterpret_cast<uint2*>(outL + o) = make_uint2(l0, l1);
}

// ---------------- weight transpose + bf16 split --------------------------------
__global__ __launch_bounds__(256)
void transsplit(const float* __restrict__ W, __nv_bfloat16* __restrict__ hiT,
                __nv_bfloat16* __restrict__ loT, int K, int N)
{
    __shared__ float tile[32][33];
    int n0 = blockIdx.x * 32, k0 = blockIdx.y * 32;
    int tx = threadIdx.x & 31, ty = threadIdx.x >> 5;
    for (int j = ty; j < 32; j += 8)
        tile[j][tx] = W[(size_t)(k0 + j) * N + n0 + tx];
    __syncthreads();
    for (int j = ty; j < 32; j += 8) {
        float x = tile[tx][j];
        __nv_bfloat16 h = __float2bfloat16(x);
        __nv_bfloat16 l = __float2bfloat16(x - __bfloat162float(h));
        size_t o = (size_t)(n0 + j) * K + k0 + tx;
        hiT[o] = h; loT[o] = l;
    }
}

// ---------------- bf16x3 HMMA GEMM, cp.async 3-stage, ldmatrix ------------------
#define ASTRIDE 40
#define PLANE_HALVES (128*ASTRIDE)
#define STG_HALVES (4*PLANE_HALVES)
#define NSTAGE 3
#define GT_SMEM_BYTES (NSTAGE*STG_HALVES*2)

__global__ __launch_bounds__(256, 1)
void gemm_bf(const __nv_bfloat16* __restrict__ Ah, const __nv_bfloat16* __restrict__ Al,
             const __nv_bfloat16* __restrict__ Bh, const __nv_bfloat16* __restrict__ Bl,
             const float* __restrict__ bias, const float* __restrict__ res,
             float* __restrict__ outF,
             __nv_bfloat16* __restrict__ outH, __nv_bfloat16* __restrict__ outL,
             int M, int N, int K, int act)
{
    extern __shared__ uint16_t sh[];
    uint32_t sb = s2u(sh);
    int tid = threadIdx.x;
    int wid = tid >> 5, lane = tid & 31;
    int g = lane >> 2, tg = lane & 3;
    int q8 = lane >> 3, e8 = lane & 7;
    int warp_m = wid & 3, warp_n = wid >> 2;
    int m0 = blockIdx.y * 128, n0 = blockIdx.x * 128;

    float acc[2][8][4];
    #pragma unroll
    for (int mt = 0; mt < 2; mt++)
        #pragma unroll
        for (int nt = 0; nt < 8; nt++)
            #pragma unroll
            for (int c = 0; c < 4; c++) acc[mt][nt][c] = 0.f;

    // cp.async per-thread coords: 8 x 16B per stage
    const __nv_bfloat16* gp[8];
    uint32_t so[8];
    #pragma unroll
    for (int u = 0; u < 8; u++) {
        int f = tid + u * 256;
        int plane = f >> 9, fr = f & 511;
        int row = fr >> 2, c = (fr & 3) << 3;
        const __nv_bfloat16* base = (plane == 0) ? Ah : (plane == 1) ? Al
                                   : (plane == 2) ? Bh : Bl;
        int grow = ((plane < 2) ? m0 : n0) + row;
        gp[u] = base + (size_t)grow * K + c;
        so[u] = (uint32_t)(plane * PLANE_HALVES + row * ASTRIDE + c) * 2;
    }
    const int T = K >> 5;

    auto issue = [&](int t) {
        uint32_t st = sb + (uint32_t)(t % NSTAGE) * (STG_HALVES * 2);
        int k0 = t << 5;
        #pragma unroll
        for (int u = 0; u < 8; u++) cp16(st + so[u], gp[u] + k0);
        cp_commit();
    };

    issue(0); issue(1);

    // fragment ldmatrix offsets (halves, before *2 and stage base)
    uint32_t aoff[2], boff[4];
    #pragma unroll
    for (int mt = 0; mt < 2; mt++)
        aoff[mt] = (uint32_t)((warp_m * 32 + mt * 16 + e8 + (q8 & 1) * 8) * ASTRIDE
                              + (q8 >> 1) * 8);
    #pragma unroll
    for (int p = 0; p < 4; p++)
        boff[p] = (uint32_t)((warp_n * 64 + (2 * p + (q8 >> 1)) * 8 + e8) * ASTRIDE
                             + (q8 & 1) * 8);

    for (int t = 0; t < T; t++) {
        if (t == T - 1) cp_wait0(); else cp_wait1();
        __syncthreads();
        if (t + 2 < T) issue(t + 2);

        uint32_t st = sb + (uint32_t)(t % NSTAGE) * (STG_HALVES * 2);
        #pragma unroll
        for (int ks = 0; ks < 32; ks += 16) {
            uint32_t ahi[2][4], alo[2][4];
            #pragma unroll
            for (int mt = 0; mt < 2; mt++) {
                ldm4(st + (aoff[mt] + ks) * 2,
                     ahi[mt][0], ahi[mt][1], ahi[mt][2], ahi[mt][3]);
                ldm4(st + (PLANE_HALVES + aoff[mt] + ks) * 2,
                     alo[mt][0], alo[mt][1], alo[mt][2], alo[mt][3]);
            }
            #pragma unroll
            for (int p = 0; p < 4; p++) {
                uint32_t bh0, bh1, bh2, bh3, bl0, bl1, bl2, bl3;
                ldm4(st + (2 * PLANE_HALVES + boff[p] + ks) * 2, bh0, bh1, bh2, bh3);
                ldm4(st + (3 * PLANE_HALVES + boff[p] + ks) * 2, bl0, bl1, bl2, bl3);
                int ntA = 2 * p, ntB = ntA + 1;
                #pragma unroll
                for (int mt = 0; mt < 2; mt++) {
                    hmma(acc[mt][ntA], ahi[mt][0], ahi[mt][1], ahi[mt][2], ahi[mt][3], bh0, bh1);
                    hmma(acc[mt][ntA], ahi[mt][0], ahi[mt][1], ahi[mt][2], ahi[mt][3], bl0, bl1);
                    hmma(acc[mt][ntA], alo[mt][0], alo[mt][1], alo[mt][2], alo[mt][3], bh0, bh1);
                    hmma(acc[mt][ntB], ahi[mt][0], ahi[mt][1], ahi[mt][2], ahi[mt][3], bh2, bh3);
                    hmma(acc[mt][ntB], ahi[mt][0], ahi[mt][1], ahi[mt][2], ahi[mt][3], bl2, bl3);
                    hmma(acc[mt][ntB], alo[mt][0], alo[mt][1], alo[mt][2], alo[mt][3], bh2, bh3);
                }
            }
        }
    }

    // ---- epilogue ----
    #pragma unroll
    for (int mt = 0; mt < 2; mt++) {
        #pragma unroll
        for (int nt = 0; nt < 8; nt++) {
            int row = m0 + warp_m * 32 + mt * 16 + g;
            int col = n0 + warp_n * 64 + nt * 8 + 2 * tg;
            #pragma unroll
            for (int half = 0; half < 2; half++) {
                int r = row + half * 8;
                float v0 = acc[mt][nt][half * 2 + 0];
                float v1 = acc[mt][nt][half * 2 + 1];
                if (bias) { v0 += bias[col]; v1 += bias[col + 1]; }
                if (act) {
                    v0 = v0 / (1.f + __expf(-v0));
                    v1 = v1 / (1.f + __expf(-v1));
                }
                size_t o = (size_t)r * N + col;
                if (outF) {
                    if (res) {
                        float2 rv = *reinterpret_cast<const float2*>(res + o);
                        v0 += rv.x; v1 += rv.y;
                    }
                    *reinterpret_cast<float2*>(outF + o) = make_float2(v0, v1);
                } else {
                    uint32_t lo;
                    uint32_t hi = split_pack(v0, v1, lo);
                    *reinterpret_cast<uint32_t*>(outH + o) = hi;
                    *reinterpret_cast<uint32_t*>(outL + o) = lo;
                }
            }
        }
    }
}

// ---------------- tensor-core flash attention (split bf16 in, cp.async) --------
#define AT_STRIDE 72
#define AT_PLANE (64*AT_STRIDE)
#define AT_SMEM_BYTES (10*AT_PLANE*2 + 3*64*4)

__global__ __launch_bounds__(128)
void attn_tc(const __nv_bfloat16* __restrict__ qh, const __nv_bfloat16* __restrict__ ql,
             const int* __restrict__ amask,
             __nv_bfloat16* __restrict__ ctxh, __nv_bfloat16* __restrict__ ctxl)
{
    extern __shared__ uint16_t ash[];
    uint32_t sb = s2u(ash);
    float* koff = reinterpret_cast<float*>(ash + 10 * AT_PLANE);  // [3][64]

    int tid = threadIdx.x;
    int lane = tid & 31, w = tid >> 5;
    int g = lane >> 2, tg = lane & 3;
    int q8 = lane >> 3, e8 = lane & 7;
    int bh = blockIdx.y;
    int b = bh >> 4, h = bh & 15;
    int qt = gridDim.x - 1 - blockIdx.x;
    int q0 = qt * 64;
    const size_t rowbase = (size_t)b * SS;
    const int hoff = h * 64;

    // cp.async coords for Q (8x16B) and KV (16x16B)
    const __nv_bfloat16* qgp[8]; uint32_t qso[8];
    #pragma unroll
    for (int u = 0; u < 8; u++) {
        int f = tid + u * 128;
        int plane = f >> 9, fr = f & 511;
        int row = fr >> 3, c = (fr & 7) << 3;
        qgp[u] = (plane ? ql : qh) + (rowbase + q0 + row) * QKVD + hoff + c;
        qso[u] = (uint32_t)(plane * AT_PLANE + row * AT_STRIDE + c) * 2;
    }
    const __nv_bfloat16* kvgp[16]; uint32_t kvso[16]; int kvrow[16];
    #pragma unroll
    for (int u = 0; u < 16; u++) {
        int f = tid + u * 128;
        int plane = f >> 9, fr = f & 511;
        int row = fr >> 3, c = (fr & 7) << 3;
        const __nv_bfloat16* base = (plane == 0) ? qh + DD : (plane == 1) ? ql + DD
                                   : (plane == 2) ? qh + 2 * DD : ql + 2 * DD;
        kvgp[u] = base + rowbase * QKVD + hoff + c;
        kvrow[u] = row;
        kvso[u] = (uint32_t)((2 + plane) * AT_PLANE + row * AT_STRIDE + c) * 2;
    }

    auto issueKV = [&](int kt) {
        uint32_t st = sb + (uint32_t)(kt & 1) * (4 * AT_PLANE * 2);
        int k0 = kt * 64;
        #pragma unroll
        for (int u = 0; u < 16; u++)
            cp16(st + kvso[u], kvgp[u] + (size_t)(k0 + kvrow[u]) * QKVD);
        cp_commit();
        if (tid < 64)
            koff[(kt % 3) * 64 + tid] = (amask[b * SS + k0 + tid] == 1) ? 0.f : NEGBIG;
    };

    // prologue: Q group, then KV tiles 0 (and 1)
    #pragma unroll
    for (int u = 0; u < 8; u++) cp16(sb + qso[u], qgp[u]);
    cp_commit();
    issueKV(0);
    if (qt >= 1) { issueKV(1); cp_wait2(); } else { cp_wait1(); }
    __syncthreads();

    // Q fragments
    uint32_t qfh[4][4], qfl[4][4];
    uint32_t qoffb = (uint32_t)((w * 16 + e8 + (q8 & 1) * 8) * AT_STRIDE + (q8 >> 1) * 8);
    #pragma unroll
    for (int kt = 0; kt < 4; kt++) {
        ldm4(sb + (qoffb + 16 * kt) * 2, qfh[kt][0], qfh[kt][1], qfh[kt][2], qfh[kt][3]);
        ldm4(sb + (AT_PLANE + qoffb + 16 * kt) * 2,
             qfl[kt][0], qfl[kt][1], qfl[kt][2], qfl[kt][3]);
    }

    // K/V frag base offsets (halves, relative to stage base)
    uint32_t kboff[4], vboff[4];
    #pragma unroll
    for (int p = 0; p < 4; p++) {
        kboff[p] = (uint32_t)(((2 * p + (q8 >> 1)) * 8 + e8) * AT_STRIDE + (q8 & 1) * 8);
        vboff[p] = (uint32_t)(((q8 & 1) * 8 + e8) * AT_STRIDE + (2 * p + (q8 >> 1)) * 8);
    }

    float o[8][4];
    #pragma unroll
    for (int nt = 0; nt < 8; nt++)
        #pragma unroll
        for (int c = 0; c < 4; c++) o[nt][c] = 0.f;
    float m0v = NEGBIG, m1v = NEGBIG, l0 = 0.f, l1 = 0.f;
    int r0g = q0 + w * 16 + g, r1g = r0g + 8;

    for (int kt_g = 0; kt_g <= qt; kt_g++) {
        int k0 = kt_g * 64;
        if (kt_g == qt) cp_wait0(); else cp_wait1();
        __syncthreads();

        uint32_t st = sb + (uint32_t)(kt_g & 1) * (4 * AT_PLANE * 2);
        uint32_t stK = st + 2 * AT_PLANE * 2;       // Kh plane
        uint32_t stKl = st + 3 * AT_PLANE * 2;
        uint32_t stV = st + 4 * AT_PLANE * 2;
        uint32_t stVl = st + 5 * AT_PLANE * 2;
        const float* kofft = koff + (kt_g % 3) * 64;

        // ---- S = Q K^T ----
        float s[8][4];
        #pragma unroll
        for (int nt = 0; nt < 8; nt++)
            #pragma unroll
            for (int c = 0; c < 4; c++) s[nt][c] = 0.f;
        #pragma unroll
        for (int kt = 0; kt < 4; kt++) {
            #pragma unroll
            for (int p = 0; p < 4; p++) {
                uint32_t bh0, bh1, bh2, bh3, bl0, bl1, bl2, bl3;
                ldm4(stK  + (kboff[p] + 16 * kt) * 2, bh0, bh1, bh2, bh3);
                ldm4(stKl + (kboff[p] + 16 * kt) * 2, bl0, bl1, bl2, bl3);
                int ntA = 2 * p, ntB = ntA + 1;
                hmma(s[ntA], qfh[kt][0], qfh[kt][1], qfh[kt][2], qfh[kt][3], bh0, bh1);
                hmma(s[ntA], qfh[kt][0], qfh[kt][1], qfh[kt][2], qfh[kt][3], bl0, bl1);
                hmma(s[ntA], qfl[kt][0], qfl[kt][1], qfl[kt][2], qfl[kt][3], bh0, bh1);
                hmma(s[ntB], qfh[kt][0], qfh[kt][1], qfh[kt][2], qfh[kt][3], bh2, bh3);
                hmma(s[ntB], qfh[kt][0], qfh[kt][1], qfh[kt][2], qfh[kt][3], bl2, bl3);
                hmma(s[ntB], qfl[kt][0], qfl[kt][1], qfl[kt][2], qfl[kt][3], bh2, bh3);
            }
        }

        // ---- scale + mask + row max ----
        bool diag = (kt_g == qt);
        float mx0 = NEGBIG, mx1 = NEGBIG;
        #pragma unroll
        for (int nt = 0; nt < 8; nt++) {
            int c0 = 8 * nt + 2 * tg;
            float kf0 = kofft[c0], kf1 = kofft[c0 + 1];
            float v0 = s[nt][0] * INV_SCALE + kf0;
            float v1 = s[nt][1] * INV_SCALE + kf1;
            float v2 = s[nt][2] * INV_SCALE + kf0;
            float v3 = s[nt][3] * INV_SCALE + kf1;
            if (diag) {
                if (k0 + c0     > r0g) v0 = NEGBIG;
                if (k0 + c0 + 1 > r0g) v1 = NEGBIG;
                if (k0 + c0     > r1g) v2 = NEGBIG;
                if (k0 + c0 + 1 > r1g) v3 = NEGBIG;
            }
            s[nt][0] = v0; s[nt][1] = v1; s[nt][2] = v2; s[nt][3] = v3;
            mx0 = fmaxf(mx0, fmaxf(v0, v1));
            mx1 = fmaxf(mx1, fmaxf(v2, v3));
        }
        mx0 = fmaxf(mx0, __shfl_xor_sync(0xffffffffu, mx0, 1));
        mx0 = fmaxf(mx0, __shfl_xor_sync(0xffffffffu, mx0, 2));
        mx1 = fmaxf(mx1, __shfl_xor_sync(0xffffffffu, mx1, 1));
        mx1 = fmaxf(mx1, __shfl_xor_sync(0xffffffffu, mx1, 2));

        float mn0 = fmaxf(m0v, mx0), mn1 = fmaxf(m1v, mx1);
        float al0 = __expf(m0v - mn0), al1 = __expf(m1v - mn1);
        m0v = mn0; m1v = mn1;
        l0 *= al0; l1 *= al1;

        #pragma unroll
        for (int nt = 0; nt < 8; nt++) {
            float p0 = __expf(s[nt][0] - m0v);
            float p1 = __expf(s[nt][1] - m0v);
            float p2 = __expf(s[nt][2] - m1v);
            float p3 = __expf(s[nt][3] - m1v);
            s[nt][0] = p0; s[nt][1] = p1; s[nt][2] = p2; s[nt][3] = p3;
            l0 += p0 + p1; l1 += p2 + p3;
        }
        #pragma unroll
        for (int nt = 0; nt < 8; nt++) {
            o[nt][0] *= al0; o[nt][1] *= al0;
            o[nt][2] *= al1; o[nt][3] *= al1;
        }

        // ---- O += P V (V via ldmatrix.trans) ----
        #pragma unroll
        for (int ktP = 0; ktP < 4; ktP++) {
            int ntA = 2 * ktP, ntB = ntA + 1;
            uint32_t a0l, a1l, a2l, a3l;
            uint32_t a0h = split_pack(s[ntA][0], s[ntA][1], a0l);
            uint32_t a1h = split_pack(s[ntA][2], s[ntA][3], a1l);
            uint32_t a2h = split_pack(s[ntB][0], s[ntB][1], a2l);
            uint32_t a3h = split_pack(s[ntB][2], s[ntB][3], a3l);
            #pragma unroll
            for (int p = 0; p < 4; p++) {
                uint32_t bh0, bh1, bh2, bh3, bl0, bl1, bl2, bl3;
                ldm4t(stV  + (vboff[p] + 16 * ktP * AT_STRIDE) * 2, bh0, bh1, bh2, bh3);
                ldm4t(stVl + (vboff[p] + 16 * ktP * AT_STRIDE) * 2, bl0, bl1, bl2, bl3);
                int n2A = 2 * p, n2B = n2A + 1;
                hmma(o[n2A], a0h, a1h, a2h, a3h, bh0, bh1);
                hmma(o[n2A], a0l, a1l, a2l, a3l, bh0, bh1);
                hmma(o[n2A], a0h, a1h, a2h, a3h, bl0, bl1);
                hmma(o[n2B], a0h, a1h, a2h, a3h, bh2, bh3);
                hmma(o[n2B], a0l, a1l, a2l, a3l, bh2, bh3);
                hmma(o[n2B], a0h, a1h, a2h, a3h, bl2, bl3);
            }
        }

        __syncthreads();
        if (kt_g + 2 <= qt) issueKV(kt_g + 2);
    }

    // ---- finalize ----
    l0 += __shfl_xor_sync(0xffffffffu, l0, 1);
    l0 += __shfl_xor_sync(0xffffffffu, l0, 2);
    l1 += __shfl_xor_sync(0xffffffffu, l1, 1);
    l1 += __shfl_xor_sync(0xffffffffu, l1, 2);
    float inv0 = 1.f / l0, inv1 = 1.f / l1;

    #pragma unroll
    for (int nt = 0; nt < 8; nt++) {
        int col = hoff + 8 * nt + 2 * tg;
        uint32_t lo0, lo1;
        uint32_t hi0 = split_pack(o[nt][0] * inv0, o[nt][1] * inv0, lo0);
        uint32_t hi1 = split_pack(o[nt][2] * inv1, o[nt][3] * inv1, lo1);
        size_t o0 = (rowbase + r0g) * DD + col;
        size_t o1 = (rowbase + r1g) * DD + col;
        *reinterpret_cast<uint32_t*>(ctxh + o0) = hi0;
        *reinterpret_cast<uint32_t*>(ctxl + o0) = lo0;
        *reinterpret_cast<uint32_t*>(ctxh + o1) = hi1;
        *reinterpret_cast<uint32_t*>(ctxl + o1) = lo1;
    }
}

// ---------------- host ---------------------------------------------------------
extern "C" void kernel_launch(void* const* d_in, const int* in_sizes, int n_in,
                              void* d_out, int out_size)
{
    const float* hidden = (const float*)d_in[0];
    const int*   amask  = (const int*)  d_in[1];
    const float* Wq     = (const float*)d_in[2];
    const float* Wk     = (const float*)d_in[3];
    const float* Wv     = (const float*)d_in[4];
    const float* Wo     = (const float*)d_in[5];
    const float* ln1g   = (const float*)d_in[6];
    const float* ln1b   = (const float*)d_in[7];
    const float* W1     = (const float*)d_in[8];
    const float* b1     = (const float*)d_in[9];
    const float* W2     = (const float*)d_in[10];
    const float* b2     = (const float*)d_in[11];
    const float* ln2g   = (const float*)d_in[12];
    const float* ln2b   = (const float*)d_in[13];
    float* out = (float*)d_out;

    __nv_bfloat16 *xh, *xl, *qh, *ql, *ch, *cl, *yh, *yl, *hh, *hl, *wT;
    float* x2;
    cudaGetSymbolAddress((void**)&xh, g_xh);
    cudaGetSymbolAddress((void**)&xl, g_xl);
    cudaGetSymbolAddress((void**)&qh, g_qh);
    cudaGetSymbolAddress((void**)&ql, g_ql);
    cudaGetSymbolAddress((void**)&ch, g_ch);
    cudaGetSymbolAddress((void**)&cl, g_cl);
    cudaGetSymbolAddress((void**)&x2, g_x2);
    cudaGetSymbolAddress((void**)&yh, g_yh);
    cudaGetSymbolAddress((void**)&yl, g_yl);
    cudaGetSymbolAddress((void**)&hh, g_hh);
    cudaGetSymbolAddress((void**)&hl, g_hl);
    cudaGetSymbolAddress((void**)&wT, g_wT);

    cudaFuncSetAttribute(attn_tc, cudaFuncAttributeMaxDynamicSharedMemorySize,
                         AT_SMEM_BYTES);
    cudaFuncSetAttribute(gemm_bf, cudaFuncAttributeMaxDynamicSharedMemorySize,
                         GT_SMEM_BYTES);

    const int M = MROWS;

    // packed QKV weights: hi rows [Wq;Wk;Wv] at 0..3M1, lo at 3M1..6M1
    transsplit<<<dim3(DD/32, DD/32), 256>>>(Wq, wT,          wT + 3*M1,  DD, DD);
    transsplit<<<dim3(DD/32, DD/32), 256>>>(Wk, wT + M1,     wT + 4*M1,  DD, DD);
    transsplit<<<dim3(DD/32, DD/32), 256>>>(Wv, wT + 2*M1,   wT + 5*M1,  DD, DD);
    transsplit<<<dim3(DD/32, DD/32), 256>>>(Wo, wT + 6*M1,   wT + 7*M1,  DD, DD);
    transsplit<<<dim3(FF/32, DD/32), 256>>>(W1, wT + 8*M1,   wT + 12*M1, DD, FF);
    transsplit<<<dim3(DD/32, FF/32), 256>>>(W2, wT + 16*M1,  wT + 20*M1, FF, DD);

    // LN1 -> split
    ln_split<<<M, 256>>>(hidden, ln1g, ln1b, xh, xl);
    // fused QKV projection -> split planes
    gemm_bf<<<dim3(QKVD/128, M/128), 256, GT_SMEM_BYTES>>>(
        xh, xl, wT, wT + 3*M1, nullptr, nullptr, nullptr, qh, ql, M, QKVD, DD, 0);
    // attention
    attn_tc<<<dim3(SS/64, BB*HH), 128, AT_SMEM_BYTES>>>(qh, ql, amask, ch, cl);
    // output projection + residual -> fp32 x2
    gemm_bf<<<dim3(DD/128, M/128), 256, GT_SMEM_BYTES>>>(
        ch, cl, wT + 6*M1, wT + 7*M1, nullptr, hidden, x2, nullptr, nullptr, M, DD, DD, 0);
    // LN2 -> split
    ln_split<<<M, 256>>>(x2, ln2g, ln2b, yh, yl);
    // FFN1 (bias + SiLU) -> split planes
    gemm_bf<<<dim3(FF/128, M/128), 256, GT_SMEM_BYTES>>>(
        yh, yl, wT + 8*M1, wT + 12*M1, b1, nullptr, nullptr, hh, hl, M, FF, DD, 1);
    // FFN2 (bias + residual x2) -> fp32 out
    gemm_bf<<<dim3(DD/128, M/128), 256, GT_SMEM_BYTES>>>(
        hh, hl, wT + 16*M1, wT + 20*M1, b2, x2, out, nullptr, nullptr, M, DD, FF, 0);
}

// round 6
// speedup vs baseline: 2.6480x; 1.0139x over previous
#include <cuda_runtime.h>
#include <cuda_bf16.h>
#include <math.h>
#include <stdint.h>

#define BB 4
#define SS 2048
#define DD 1024
#define FF 4096
#define HH 16
#define QKVD (3*DD)
#define INV_SCALE 0.125f
#define NEGBIG -1e30f
#define MROWS (BB*SS)
#define M1 (DD*DD)

// ---------------- scratch: split bf16 activation planes ------------------------
__device__ __nv_bfloat16 g_xh [MROWS*DD];
__device__ __nv_bfloat16 g_xl [MROWS*DD];
__device__ __nv_bfloat16 g_qh [MROWS*QKVD];
__device__ __nv_bfloat16 g_ql [MROWS*QKVD];
__device__ __nv_bfloat16 g_ch [MROWS*DD];
__device__ __nv_bfloat16 g_cl [MROWS*DD];
__device__ float         g_x2 [MROWS*DD];
__device__ __nv_bfloat16 g_yh [MROWS*DD];
__device__ __nv_bfloat16 g_yl [MROWS*DD];
__device__ __nv_bfloat16 g_hh [MROWS*FF];
__device__ __nv_bfloat16 g_hl [MROWS*FF];
__device__ __nv_bfloat16 g_wT [24*M1];

// ---------------- helpers ------------------------------------------------------
__device__ __forceinline__ uint32_t split_pack(float a, float b, uint32_t& lo) {
    __nv_bfloat16 ha = __float2bfloat16(a), hb = __float2bfloat16(b);
    __nv_bfloat16 la = __float2bfloat16(a - __bfloat162float(ha));
    __nv_bfloat16 lb = __float2bfloat16(b - __bfloat162float(hb));
    lo = (uint32_t)__bfloat16_as_ushort(la) | ((uint32_t)__bfloat16_as_ushort(lb) << 16);
    return (uint32_t)__bfloat16_as_ushort(ha) | ((uint32_t)__bfloat16_as_ushort(hb) << 16);
}
__device__ __forceinline__ void hmma(float* d, uint32_t a0, uint32_t a1,
                                     uint32_t a2, uint32_t a3,
                                     uint32_t b0, uint32_t b1) {
    asm volatile("mma.sync.aligned.m16n8k16.row.col.f32.bf16.bf16.f32 "
                 "{%0,%1,%2,%3}, {%4,%5,%6,%7}, {%8,%9}, {%0,%1,%2,%3};"
                 : "+f"(d[0]), "+f"(d[1]), "+f"(d[2]), "+f"(d[3])
                 : "r"(a0), "r"(a1), "r"(a2), "r"(a3), "r"(b0), "r"(b1));
}
__device__ __forceinline__ uint32_t s2u(const void* p) {
    return (uint32_t)__cvta_generic_to_shared(p);
}
__device__ __forceinline__ void cp16(uint32_t dst, const void* src) {
    asm volatile("cp.async.ca.shared.global [%0], [%1], 16;" :: "r"(dst), "l"(src));
}
__device__ __forceinline__ void cp_commit() { asm volatile("cp.async.commit_group;"); }
__device__ __forceinline__ void cp_wait0()  { asm volatile("cp.async.wait_group 0;"); }
__device__ __forceinline__ void cp_wait1()  { asm volatile("cp.async.wait_group 1;"); }
__device__ __forceinline__ void ldm4(uint32_t addr, uint32_t& r0, uint32_t& r1,
                                     uint32_t& r2, uint32_t& r3) {
    asm volatile("ldmatrix.sync.aligned.m8n8.x4.shared.b16 {%0,%1,%2,%3}, [%4];"
                 : "=r"(r0), "=r"(r1), "=r"(r2), "=r"(r3) : "r"(addr));
}
__device__ __forceinline__ void ldm4t(uint32_t addr, uint32_t& r0, uint32_t& r1,
                                      uint32_t& r2, uint32_t& r3) {
    asm volatile("ldmatrix.sync.aligned.m8n8.x4.trans.shared.b16 {%0,%1,%2,%3}, [%4];"
                 : "=r"(r0), "=r"(r1), "=r"(r2), "=r"(r3) : "r"(addr));
}

// ---------------- LayerNorm with split bf16 output -----------------------------
__global__ __launch_bounds__(256)
void ln_split(const float* __restrict__ x, const float* __restrict__ g,
              const float* __restrict__ b, __nv_bfloat16* __restrict__ outH,
              __nv_bfloat16* __restrict__ outL)
{
    int row = blockIdx.x;
    int tid = threadIdx.x;
    const float* xr = x + (size_t)row * DD;
    float4 v = *reinterpret_cast<const float4*>(xr + tid * 4);
    float s  = v.x + v.y + v.z + v.w;
    float sq = v.x*v.x + v.y*v.y + v.z*v.z + v.w*v.w;
    #pragma unroll
    for (int o = 16; o > 0; o >>= 1) {
        s  += __shfl_xor_sync(0xffffffffu, s,  o);
        sq += __shfl_xor_sync(0xffffffffu, sq, o);
    }
    __shared__ float ws[8], wq[8];
    __shared__ float smean, srstd;
    int wid = tid >> 5, lane = tid & 31;
    if (lane == 0) { ws[wid] = s; wq[wid] = sq; }
    __syncthreads();
    if (tid == 0) {
        float S = 0.f, Q = 0.f;
        #pragma unroll
        for (int i = 0; i < 8; i++) { S += ws[i]; Q += wq[i]; }
        float mean = S * (1.f / DD);
        float var  = fmaxf(Q * (1.f / DD) - mean * mean, 0.f);
        smean = mean;
        srstd = rsqrtf(var + 1e-12f);
    }
    __syncthreads();
    float mean = smean, rstd = srstd;
    float4 gv = *reinterpret_cast<const float4*>(g + tid * 4);
    float4 bv = *reinterpret_cast<const float4*>(b + tid * 4);
    float o0 = (v.x - mean) * rstd * gv.x + bv.x;
    float o1 = (v.y - mean) * rstd * gv.y + bv.y;
    float o2 = (v.z - mean) * rstd * gv.z + bv.z;
    float o3 = (v.w - mean) * rstd * gv.w + bv.w;
    uint32_t l0, l1;
    uint32_t h0 = split_pack(o0, o1, l0);
    uint32_t h1 = split_pack(o2, o3, l1);
    size_t o = (size_t)row * DD + tid * 4;
    *reinterpret_cast<uint2*>(outH + o) = make_uint2(h0, h1);
    *reinterpret_cast<uint2*>(outL + o) = make_uint2(l0, l1);
}

// ---------------- weight transpose + bf16 split --------------------------------
__global__ __launch_bounds__(256)
void transsplit(const float* __restrict__ W, __nv_bfloat16* __restrict__ hiT,
                __nv_bfloat16* __restrict__ loT, int K, int N)
{
    __shared__ float tile[32][33];
    int n0 = blockIdx.x * 32, k0 = blockIdx.y * 32;
    int tx = threadIdx.x & 31, ty = threadIdx.x >> 5;
    for (int j = ty; j < 32; j += 8)
        tile[j][tx] = W[(size_t)(k0 + j) * N + n0 + tx];
    __syncthreads();
    for (int j = ty; j < 32; j += 8) {
        float x = tile[tx][j];
        __nv_bfloat16 h = __float2bfloat16(x);
        __nv_bfloat16 l = __float2bfloat16(x - __bfloat162float(h));
        size_t o = (size_t)(n0 + j) * K + k0 + tx;
        hiT[o] = h; loT[o] = l;
    }
}

// ---------------- bf16x3 HMMA GEMM: 256x128 tile, 512 threads, 2-stage ----------
#define ASTRIDE 40
#define A_PLANE (256*ASTRIDE)
#define B_PLANE (128*ASTRIDE)
#define STG_HALVES (2*A_PLANE + 2*B_PLANE)
#define GT_SMEM_BYTES (2*STG_HALVES*2)

__global__ __launch_bounds__(512, 1)
void gemm_bf(const __nv_bfloat16* __restrict__ Ah, const __nv_bfloat16* __restrict__ Al,
             const __nv_bfloat16* __restrict__ Bh, const __nv_bfloat16* __restrict__ Bl,
             const float* __restrict__ bias, const float* __restrict__ res,
             float* __restrict__ outF,
             __nv_bfloat16* __restrict__ outH, __nv_bfloat16* __restrict__ outL,
             int M, int N, int K, int act)
{
    extern __shared__ uint16_t sh[];
    uint32_t sb = s2u(sh);
    int tid = threadIdx.x;
    int wid = tid >> 5, lane = tid & 31;
    int g = lane >> 2, tg = lane & 3;
    int q8 = lane >> 3, e8 = lane & 7;
    int warp_m = wid & 3, warp_n = wid >> 2;   // 4 x 4 warps
    int m0 = blockIdx.y * 256, n0 = blockIdx.x * 128;

    float acc[4][4][4];
    #pragma unroll
    for (int mt = 0; mt < 4; mt++)
        #pragma unroll
        for (int nt = 0; nt < 4; nt++)
            #pragma unroll
            for (int c = 0; c < 4; c++) acc[mt][nt][c] = 0.f;

    // cp.async: 3072 chunks of 16B per stage -> 6 per thread
    const __nv_bfloat16* gp[6];
    uint32_t so[6];
    #pragma unroll
    for (int u = 0; u < 6; u++) {
        int f = tid + u * 512;
        if (f < 2048) {
            int plane = f >> 10, fr = f & 1023;
            int row = fr >> 2, c = (fr & 3) << 3;
            gp[u] = (plane ? Al : Ah) + (size_t)(m0 + row) * K + c;
            so[u] = (uint32_t)(plane * A_PLANE + row * ASTRIDE + c) * 2;
        } else {
            int fb = f - 2048;
            int plane = fb >> 9, fr = fb & 511;
            int row = fr >> 2, c = (fr & 3) << 3;
            gp[u] = (plane ? Bl : Bh) + (size_t)(n0 + row) * K + c;
            so[u] = (uint32_t)(2 * A_PLANE + plane * B_PLANE + row * ASTRIDE + c) * 2;
        }
    }
    const int T = K >> 5;

    auto issue = [&](int t) {
        uint32_t st = sb + (uint32_t)(t & 1) * (STG_HALVES * 2);
        int k0 = t << 5;
        #pragma unroll
        for (int u = 0; u < 6; u++) cp16(st + so[u], gp[u] + k0);
        cp_commit();
    };

    issue(0);

    // fragment ldmatrix offsets (halves, relative to stage base)
    uint32_t aoff[4], boff[2];
    #pragma unroll
    for (int mt = 0; mt < 4; mt++)
        aoff[mt] = (uint32_t)((warp_m * 64 + mt * 16 + e8 + (q8 & 1) * 8) * ASTRIDE
                              + (q8 >> 1) * 8);
    #pragma unroll
    for (int p = 0; p < 2; p++)
        boff[p] = (uint32_t)((warp_n * 32 + (2 * p + (q8 >> 1)) * 8 + e8) * ASTRIDE
                             + (q8 & 1) * 8);

    for (int t = 0; t < T; t++) {
        cp_wait0();
        __syncthreads();
        if (t + 1 < T) issue(t + 1);

        uint32_t st = sb + (uint32_t)(t & 1) * (STG_HALVES * 2);
        #pragma unroll
        for (int ks = 0; ks < 32; ks += 16) {
            uint32_t ahi[4][4], alo[4][4];
            #pragma unroll
            for (int mt = 0; mt < 4; mt++) {
                ldm4(st + (aoff[mt] + ks) * 2,
                     ahi[mt][0], ahi[mt][1], ahi[mt][2], ahi[mt][3]);
                ldm4(st + (A_PLANE + aoff[mt] + ks) * 2,
                     alo[mt][0], alo[mt][1], alo[mt][2], alo[mt][3]);
            }
            #pragma unroll
            for (int p = 0; p < 2; p++) {
                uint32_t bh0, bh1, bh2, bh3, bl0, bl1, bl2, bl3;
                ldm4(st + (2 * A_PLANE + boff[p] + ks) * 2, bh0, bh1, bh2, bh3);
                ldm4(st + (2 * A_PLANE + B_PLANE + boff[p] + ks) * 2, bl0, bl1, bl2, bl3);
                int ntA = 2 * p, ntB = ntA + 1;
                #pragma unroll
                for (int mt = 0; mt < 4; mt++) {
                    hmma(acc[mt][ntA], ahi[mt][0], ahi[mt][1], ahi[mt][2], ahi[mt][3], bh0, bh1);
                    hmma(acc[mt][ntA], ahi[mt][0], ahi[mt][1], ahi[mt][2], ahi[mt][3], bl0, bl1);
                    hmma(acc[mt][ntA], alo[mt][0], alo[mt][1], alo[mt][2], alo[mt][3], bh0, bh1);
                    hmma(acc[mt][ntB], ahi[mt][0], ahi[mt][1], ahi[mt][2], ahi[mt][3], bh2, bh3);
                    hmma(acc[mt][ntB], ahi[mt][0], ahi[mt][1], ahi[mt][2], ahi[mt][3], bl2, bl3);
                    hmma(acc[mt][ntB], alo[mt][0], alo[mt][1], alo[mt][2], alo[mt][3], bh2, bh3);
                }
            }
        }
    }

    // ---- epilogue ----
    #pragma unroll
    for (int mt = 0; mt < 4; mt++) {
        #pragma unroll
        for (int nt = 0; nt < 4; nt++) {
            int row = m0 + warp_m * 64 + mt * 16 + g;
            int col = n0 + warp_n * 32 + nt * 8 + 2 * tg;
            #pragma unroll
            for (int half = 0; half < 2; half++) {
                int r = row + half * 8;
                float v0 = acc[mt][nt][half * 2 + 0];
                float v1 = acc[mt][nt][half * 2 + 1];
                if (bias) { v0 += bias[col]; v1 += bias[col + 1]; }
                if (act) {
                    v0 = v0 / (1.f + __expf(-v0));
                    v1 = v1 / (1.f + __expf(-v1));
                }
                size_t o = (size_t)r * N + col;
                if (outF) {
                    if (res) {
                        float2 rv = *reinterpret_cast<const float2*>(res + o);
                        v0 += rv.x; v1 += rv.y;
                    }
                    *reinterpret_cast<float2*>(outF + o) = make_float2(v0, v1);
                } else {
                    uint32_t lo;
                    uint32_t hi = split_pack(v0, v1, lo);
                    *reinterpret_cast<uint32_t*>(outH + o) = hi;
                    *reinterpret_cast<uint32_t*>(outL + o) = lo;
                }
            }
        }
    }
}

// ---------------- tensor-core flash attention: 128 q-rows, 256 threads ----------
#define AT_STRIDE 72
#define QPB (128*AT_STRIDE*2)        // Q plane bytes
#define KPB (64*AT_STRIDE*2)         // K/V plane bytes
#define KV_BASE (2*QPB)
#define AT_SMEM_BYTES (KV_BASE + 8*KPB + 3*64*4)

__global__ __launch_bounds__(256)
void attn_tc(const __nv_bfloat16* __restrict__ qh, const __nv_bfloat16* __restrict__ ql,
             const int* __restrict__ amask,
             __nv_bfloat16* __restrict__ ctxh, __nv_bfloat16* __restrict__ ctxl)
{
    extern __shared__ uint16_t ash[];
    uint32_t sb = s2u(ash);
    float* koff = reinterpret_cast<float*>((char*)ash + KV_BASE + 8 * KPB);

    int tid = threadIdx.x;
    int lane = tid & 31, w = tid >> 5;        // 8 warps, 16 q-rows each
    int g = lane >> 2, tg = lane & 3;
    int q8 = lane >> 3, e8 = lane & 7;
    int bh = blockIdx.y;
    int b = bh >> 4, h = bh & 15;
    int qt = gridDim.x - 1 - blockIdx.x;      // heavy blocks first
    int q0 = qt * 128;
    const size_t rowbase = (size_t)b * SS;
    const int hoff = h * 64;
    const int ktmax = 2 * qt + 1;

    // Q cp coords: 2048 chunks -> 8/thread
    const __nv_bfloat16* qgp[8]; uint32_t qso[8];
    #pragma unroll
    for (int u = 0; u < 8; u++) {
        int f = tid + u * 256;
        int plane = f >> 10, fr = f & 1023;
        int row = fr >> 3, c = (fr & 7) << 3;
        qgp[u] = (plane ? ql : qh) + (rowbase + q0 + row) * QKVD + hoff + c;
        qso[u] = (uint32_t)(plane * (QPB / 2) + row * AT_STRIDE + c) * 2;
    }
    // KV cp coords: 2048 chunks/buffer -> 8/thread
    const __nv_bfloat16* kvgp[8]; uint32_t kvso[8]; int kvrow[8];
    #pragma unroll
    for (int u = 0; u < 8; u++) {
        int f = tid + u * 256;
        int plane = f >> 9, fr = f & 511;      // 0=Kh 1=Kl 2=Vh 3=Vl
        int row = fr >> 3, c = (fr & 7) << 3;
        const __nv_bfloat16* base = (plane == 0) ? qh + DD : (plane == 1) ? ql + DD
                                   : (plane == 2) ? qh + 2 * DD : ql + 2 * DD;
        kvgp[u] = base + rowbase * QKVD + hoff + c;
        kvrow[u] = row;
        kvso[u] = (uint32_t)KV_BASE + (uint32_t)(plane * (KPB / 2) + row * AT_STRIDE + c) * 2;
    }

    auto issueKV = [&](int kt) {
        uint32_t st = sb + (uint32_t)(kt & 1) * (4 * KPB);
        int k0 = kt * 64;
        #pragma unroll
        for (int u = 0; u < 8; u++)
            cp16(st + kvso[u], kvgp[u] + (size_t)(k0 + kvrow[u]) * QKVD);
        cp_commit();
        if (tid < 64)
            koff[(kt % 3) * 64 + tid] = (amask[b * SS + k0 + tid] == 1) ? 0.f : NEGBIG;
    };

    // prologue: Q, KV0, KV1 (ktmax >= 1 always)
    #pragma unroll
    for (int u = 0; u < 8; u++) cp16(sb + qso[u], qgp[u]);
    cp_commit();
    issueKV(0);
    issueKV(1);
    cp_wait1();
    __syncthreads();

    // Q fragments
    uint32_t qfh[4][4], qfl[4][4];
    uint32_t qoffb = (uint32_t)((w * 16 + e8 + (q8 & 1) * 8) * AT_STRIDE + (q8 >> 1) * 8);
    #pragma unroll
    for (int kt = 0; kt < 4; kt++) {
        ldm4(sb + (qoffb + 16 * kt) * 2, qfh[kt][0], qfh[kt][1], qfh[kt][2], qfh[kt][3]);
        ldm4(sb + QPB + (qoffb + 16 * kt) * 2,
             qfl[kt][0], qfl[kt][1], qfl[kt][2], qfl[kt][3]);
    }

    uint32_t kboff[4], vboff[4];
    #pragma unroll
    for (int p = 0; p < 4; p++) {
        kboff[p] = (uint32_t)(((2 * p + (q8 >> 1)) * 8 + e8) * AT_STRIDE + (q8 & 1) * 8);
        vboff[p] = (uint32_t)(((q8 & 1) * 8 + e8) * AT_STRIDE + (2 * p + (q8 >> 1)) * 8);
    }

    float o[8][4];
    #pragma unroll
    for (int nt = 0; nt < 8; nt++)
        #pragma unroll
        for (int c = 0; c < 4; c++) o[nt][c] = 0.f;
    float m0v = NEGBIG, m1v = NEGBIG, l0 = 0.f, l1 = 0.f;
    int r0g = q0 + w * 16 + g, r1g = r0g + 8;

    for (int kt_g = 0; kt_g <= ktmax; kt_g++) {
        int k0 = kt_g * 64;
        if (kt_g == ktmax) cp_wait0(); else cp_wait1();
        __syncthreads();

        uint32_t st = sb + (uint32_t)(kt_g & 1) * (4 * KPB);
        uint32_t stK  = st + KV_BASE;
        uint32_t stKl = stK + KPB;
        uint32_t stV  = stK + 2 * KPB;
        uint32_t stVl = stK + 3 * KPB;
        const float* kofft = koff + (kt_g % 3) * 64;

        // ---- S = Q K^T ----
        float s[8][4];
        #pragma unroll
        for (int nt = 0; nt < 8; nt++)
            #pragma unroll
            for (int c = 0; c < 4; c++) s[nt][c] = 0.f;
        #pragma unroll
        for (int kt = 0; kt < 4; kt++) {
            #pragma unroll
            for (int p = 0; p < 4; p++) {
                uint32_t bh0, bh1, bh2, bh3, bl0, bl1, bl2, bl3;
                ldm4(stK  + (kboff[p] + 16 * kt) * 2, bh0, bh1, bh2, bh3);
                ldm4(stKl + (kboff[p] + 16 * kt) * 2, bl0, bl1, bl2, bl3);
                int ntA = 2 * p, ntB = ntA + 1;
                hmma(s[ntA], qfh[kt][0], qfh[kt][1], qfh[kt][2], qfh[kt][3], bh0, bh1);
                hmma(s[ntA], qfh[kt][0], qfh[kt][1], qfh[kt][2], qfh[kt][3], bl0, bl1);
                hmma(s[ntA], qfl[kt][0], qfl[kt][1], qfl[kt][2], qfl[kt][3], bh0, bh1);
                hmma(s[ntB], qfh[kt][0], qfh[kt][1], qfh[kt][2], qfh[kt][3], bh2, bh3);
                hmma(s[ntB], qfh[kt][0], qfh[kt][1], qfh[kt][2], qfh[kt][3], bl2, bl3);
                hmma(s[ntB], qfl[kt][0], qfl[kt][1], qfl[kt][2], qfl[kt][3], bh2, bh3);
            }
        }

        // ---- scale + mask + row max (mask unconditional) ----
        float mx0 = NEGBIG, mx1 = NEGBIG;
        #pragma unroll
        for (int nt = 0; nt < 8; nt++) {
            int c0 = k0 + 8 * nt + 2 * tg;
            float kf0 = kofft[8 * nt + 2 * tg], kf1 = kofft[8 * nt + 2 * tg + 1];
            float v0 = s[nt][0] * INV_SCALE + kf0;
            float v1 = s[nt][1] * INV_SCALE + kf1;
            float v2 = s[nt][2] * INV_SCALE + kf0;
            float v3 = s[nt][3] * INV_SCALE + kf1;
            if (c0     > r0g) v0 = NEGBIG;
            if (c0 + 1 > r0g) v1 = NEGBIG;
            if (c0     > r1g) v2 = NEGBIG;
            if (c0 + 1 > r1g) v3 = NEGBIG;
            s[nt][0] = v0; s[nt][1] = v1; s[nt][2] = v2; s[nt][3] = v3;
            mx0 = fmaxf(mx0, fmaxf(v0, v1));
            mx1 = fmaxf(mx1, fmaxf(v2, v3));
        }
        mx0 = fmaxf(mx0, __shfl_xor_sync(0xffffffffu, mx0, 1));
        mx0 = fmaxf(mx0, __shfl_xor_sync(0xffffffffu, mx0, 2));
        mx1 = fmaxf(mx1, __shfl_xor_sync(0xffffffffu, mx1, 1));
        mx1 = fmaxf(mx1, __shfl_xor_sync(0xffffffffu, mx1, 2));

        float mn0 = fmaxf(m0v, mx0), mn1 = fmaxf(m1v, mx1);
        float al0 = __expf(m0v - mn0), al1 = __expf(m1v - mn1);
        m0v = mn0; m1v = mn1;
        l0 *= al0; l1 *= al1;

        #pragma unroll
        for (int nt = 0; nt < 8; nt++) {
            float p0 = __expf(s[nt][0] - m0v);
            float p1 = __expf(s[nt][1] - m0v);
            float p2 = __expf(s[nt][2] - m1v);
            float p3 = __expf(s[nt][3] - m1v);
            s[nt][0] = p0; s[nt][1] = p1; s[nt][2] = p2; s[nt][3] = p3;
            l0 += p0 + p1; l1 += p2 + p3;
        }
        #pragma unroll
        for (int nt = 0; nt < 8; nt++) {
            o[nt][0] *= al0; o[nt][1] *= al0;
            o[nt][2] *= al1; o[nt][3] *= al1;
        }

        // ---- O += P V ----
        #pragma unroll
        for (int ktP = 0; ktP < 4; ktP++) {
            int ntA = 2 * ktP, ntB = ntA + 1;
            uint32_t a0l, a1l, a2l, a3l;
            uint32_t a0h = split_pack(s[ntA][0], s[ntA][1], a0l);
            uint32_t a1h = split_pack(s[ntA][2], s[ntA][3], a1l);
            uint32_t a2h = split_pack(s[ntB][0], s[ntB][1], a2l);
            uint32_t a3h = split_pack(s[ntB][2], s[ntB][3], a3l);
            #pragma unroll
            for (int p = 0; p < 4; p++) {
                uint32_t bh0, bh1, bh2, bh3, bl0, bl1, bl2, bl3;
                ldm4t(stV  + (vboff[p] + 16 * ktP * AT_STRIDE) * 2, bh0, bh1, bh2, bh3);
                ldm4t(stVl + (vboff[p] + 16 * ktP * AT_STRIDE) * 2, bl0, bl1, bl2, bl3);
                int n2A = 2 * p, n2B = n2A + 1;
                hmma(o[n2A], a0h, a1h, a2h, a3h, bh0, bh1);
                hmma(o[n2A], a0l, a1l, a2l, a3l, bh0, bh1);
                hmma(o[n2A], a0h, a1h, a2h, a3h, bl0, bl1);
                hmma(o[n2B], a0h, a1h, a2h, a3h, bh2, bh3);
                hmma(o[n2B], a0l, a1l, a2l, a3l, bh2, bh3);
                hmma(o[n2B], a0h, a1h, a2h, a3h, bl2, bl3);
            }
        }

        __syncthreads();
        if (kt_g + 2 <= ktmax) issueKV(kt_g + 2);
    }

    // ---- finalize ----
    l0 += __shfl_xor_sync(0xffffffffu, l0, 1);
    l0 += __shfl_xor_sync(0xffffffffu, l0, 2);
    l1 += __shfl_xor_sync(0xffffffffu, l1, 1);
    l1 += __shfl_xor_sync(0xffffffffu, l1, 2);
    float inv0 = 1.f / l0, inv1 = 1.f / l1;

    #pragma unroll
    for (int nt = 0; nt < 8; nt++) {
        int col = hoff + 8 * nt + 2 * tg;
        uint32_t lo0, lo1;
        uint32_t hi0 = split_pack(o[nt][0] * inv0, o[nt][1] * inv0, lo0);
        uint32_t hi1 = split_pack(o[nt][2] * inv1, o[nt][3] * inv1, lo1);
        size_t o0 = (rowbase + r0g) * DD + col;
        size_t o1 = (rowbase + r1g) * DD + col;
        *reinterpret_cast<uint32_t*>(ctxh + o0) = hi0;
        *reinterpret_cast<uint32_t*>(ctxl + o0) = lo0;
        *reinterpret_cast<uint32_t*>(ctxh + o1) = hi1;
        *reinterpret_cast<uint32_t*>(ctxl + o1) = lo1;
    }
}

// ---------------- host ---------------------------------------------------------
extern "C" void kernel_launch(void* const* d_in, const int* in_sizes, int n_in,
                              void* d_out, int out_size)
{
    const float* hidden = (const float*)d_in[0];
    const int*   amask  = (const int*)  d_in[1];
    const float* Wq     = (const float*)d_in[2];
    const float* Wk     = (const float*)d_in[3];
    const float* Wv     = (const float*)d_in[4];
    const float* Wo     = (const float*)d_in[5];
    const float* ln1g   = (const float*)d_in[6];
    const float* ln1b   = (const float*)d_in[7];
    const float* W1     = (const float*)d_in[8];
    const float* b1     = (const float*)d_in[9];
    const float* W2     = (const float*)d_in[10];
    const float* b2     = (const float*)d_in[11];
    const float* ln2g   = (const float*)d_in[12];
    const float* ln2b   = (const float*)d_in[13];
    float* out = (float*)d_out;

    __nv_bfloat16 *xh, *xl, *qh, *ql, *ch, *cl, *yh, *yl, *hh, *hl, *wT;
    float* x2;
    cudaGetSymbolAddress((void**)&xh, g_xh);
    cudaGetSymbolAddress((void**)&xl, g_xl);
    cudaGetSymbolAddress((void**)&qh, g_qh);
    cudaGetSymbolAddress((void**)&ql, g_ql);
    cudaGetSymbolAddress((void**)&ch, g_ch);
    cudaGetSymbolAddress((void**)&cl, g_cl);
    cudaGetSymbolAddress((void**)&x2, g_x2);
    cudaGetSymbolAddress((void**)&yh, g_yh);
    cudaGetSymbolAddress((void**)&yl, g_yl);
    cudaGetSymbolAddress((void**)&hh, g_hh);
    cudaGetSymbolAddress((void**)&hl, g_hl);
    cudaGetSymbolAddress((void**)&wT, g_wT);

    cudaFuncSetAttribute(attn_tc, cudaFuncAttributeMaxDynamicSharedMemorySize,
                         AT_SMEM_BYTES);
    cudaFuncSetAttribute(gemm_bf, cudaFuncAttributeMaxDynamicSharedMemorySize,
                         GT_SMEM_BYTES);

    const int M = MROWS;

    transsplit<<<dim3(DD/32, DD/32), 256>>>(Wq, wT,          wT + 3*M1,  DD, DD);
    transsplit<<<dim3(DD/32, DD/32), 256>>>(Wk, wT + M1,     wT + 4*M1,  DD, DD);
    transsplit<<<dim3(DD/32, DD/32), 256>>>(Wv, wT + 2*M1,   wT + 5*M1,  DD, DD);
    transsplit<<<dim3(DD/32, DD/32), 256>>>(Wo, wT + 6*M1,   wT + 7*M1,  DD, DD);
    transsplit<<<dim3(FF/32, DD/32), 256>>>(W1, wT + 8*M1,   wT + 12*M1, DD, FF);
    transsplit<<<dim3(DD/32, FF/32), 256>>>(W2, wT + 16*M1,  wT + 20*M1, FF, DD);

    // LN1 -> split
    ln_split<<<M, 256>>>(hidden, ln1g, ln1b, xh, xl);
    // fused QKV projection -> split planes
    gemm_bf<<<dim3(QKVD/128, M/256), 512, GT_SMEM_BYTES>>>(
        xh, xl, wT, wT + 3*M1, nullptr, nullptr, nullptr, qh, ql, M, QKVD, DD, 0);
    // attention
    attn_tc<<<dim3(SS/128, BB*HH), 256, AT_SMEM_BYTES>>>(qh, ql, amask, ch, cl);
    // output projection + residual -> fp32 x2
    gemm_bf<<<dim3(DD/128, M/256), 512, GT_SMEM_BYTES>>>(
        ch, cl, wT + 6*M1, wT + 7*M1, nullptr, hidden, x2, nullptr, nullptr, M, DD, DD, 0);
    // LN2 -> split
    ln_split<<<M, 256>>>(x2, ln2g, ln2b, yh, yl);
    // FFN1 (bias + SiLU) -> split planes
    gemm_bf<<<dim3(FF/128, M/256), 512, GT_SMEM_BYTES>>>(
        yh, yl, wT + 8*M1, wT + 12*M1, b1, nullptr, nullptr, hh, hl, M, FF, DD, 1);
    // FFN2 (bias + residual x2) -> fp32 out
    gemm_bf<<<dim3(DD/128, M/256), 512, GT_SMEM_BYTES>>>(
        hh, hl, wT + 16*M1, wT + 20*M1, b2, x2, out, nullptr, nullptr, M, DD, FF, 0);
}